// round 1
// baseline (speedup 1.0000x reference)
#include <cuda_runtime.h>
#include <math.h>

#define NB 4
#define NS 2048
#define NH 2048
#define NF 5632
#define NE 8
#define NT (NB * NS)   /* 8192 tokens */
#define NP (NT * 2)    /* 16384 (token, expert) pairs */

// ---------------- scratch (device globals; no runtime allocation) ----------
__device__ float g_h1[(size_t)NP * NF];   // silu(x gW^T) * (x uW^T), per pair row
__device__ float g_ho[(size_t)NP * NH];   // h1 dW^T + b, per pair row
__device__ int   g_top_i[NP];
__device__ float g_top_w[NP];
__device__ int   g_pair_token[NP];        // pair row -> token
__device__ int   g_token_pair[NP];        // token slot k -> pair row
__device__ int   g_counts[NE];
__device__ int   g_offsets[NE];
__device__ int   g_cursor[NE];

// ---------------- init ------------------------------------------------------
__global__ void init_k() {
    if (threadIdx.x < NE) g_counts[threadIdx.x] = 0;
}

// ---------------- router: logits, top-2, softmax weights --------------------
__global__ void router_k(const float* __restrict__ x,
                         const float* __restrict__ rW,
                         const int* __restrict__ elim_p,
                         float* __restrict__ logits_out) {
    const int gwarp = (blockIdx.x * blockDim.x + threadIdx.x) >> 5;
    const int lane  = threadIdx.x & 31;
    if (gwarp >= NT) return;

    const float* xr = x + (size_t)gwarp * NH;
    float acc[NE];
#pragma unroll
    for (int e = 0; e < NE; ++e) acc[e] = 0.f;

    for (int h = lane; h < NH; h += 32) {
        const float xv = xr[h];
#pragma unroll
        for (int e = 0; e < NE; ++e)
            acc[e] = fmaf(xv, rW[e * NH + h], acc[e]);
    }
#pragma unroll
    for (int e = 0; e < NE; ++e) {
#pragma unroll
        for (int o = 16; o > 0; o >>= 1)
            acc[e] += __shfl_xor_sync(0xffffffffu, acc[e], o);
    }

    if (lane == 0) {
        const int elim = *elim_p;
#pragma unroll
        for (int e = 0; e < NE; ++e)
            if (e >= elim) acc[e] = -INFINITY;
        // write logits section of output
#pragma unroll
        for (int e = 0; e < NE; ++e)
            logits_out[gwarp * NE + e] = acc[e];

        // top-1 (lowest index wins ties, matching lax.top_k)
        int i0 = 0; float v0 = acc[0];
        for (int e = 1; e < NE; ++e)
            if (acc[e] > v0) { v0 = acc[e]; i0 = e; }
        // top-2
        int i1 = -1; float v1 = -INFINITY;
        for (int e = 0; e < NE; ++e) {
            if (e == i0) continue;
            if (acc[e] > v1) { v1 = acc[e]; i1 = e; }
        }
        float w0, w1;
        if (i1 < 0) { i1 = (i0 + 1) & (NE - 1); w0 = 1.f; w1 = 0.f; }
        else {
            const float ex = expf(v1 - v0);  // v1 <= v0 -> stable
            w0 = 1.f / (1.f + ex);
            w1 = ex  / (1.f + ex);
        }
        g_top_i[gwarp * 2 + 0] = i0;
        g_top_i[gwarp * 2 + 1] = i1;
        g_top_w[gwarp * 2 + 0] = w0;
        g_top_w[gwarp * 2 + 1] = w1;
        atomicAdd(&g_counts[i0], 1);
        atomicAdd(&g_counts[i1], 1);
    }
}

// ---------------- exclusive scan over 8 counts ------------------------------
__global__ void scan_k() {
    if (threadIdx.x == 0) {
        int o = 0;
        for (int e = 0; e < NE; ++e) {
            g_offsets[e] = o;
            o += g_counts[e];
            g_cursor[e] = 0;
        }
    }
}

// ---------------- scatter tokens into per-expert pair lists -----------------
__global__ void scatter_k() {
    const int t = blockIdx.x * blockDim.x + threadIdx.x;
    if (t >= NT) return;
#pragma unroll
    for (int k = 0; k < 2; ++k) {
        const int e   = g_top_i[t * 2 + k];
        const int pos = g_offsets[e] + atomicAdd(&g_cursor[e], 1);
        g_pair_token[pos]       = t;
        g_token_pair[t * 2 + k] = pos;
    }
}

// ---------------- GEMM1: h1 = silu(x gW^T) * (x uW^T), gathered rows --------
// tile: 128 tokens x 64 F-cols, BK=16, 256 threads, 8x4 microtile per matrix
__global__ void __launch_bounds__(256, 2)
gemm1_k(const float* __restrict__ x,
        const float* __restrict__ gW,
        const float* __restrict__ uW) {
    const int e   = blockIdx.z;
    const int cnt = g_counts[e];
    const int m0  = blockIdx.x * 128;
    if (m0 >= cnt) return;
    const int off = g_offsets[e];
    const int f0  = blockIdx.y * 64;

    __shared__ float As[2][16][128];
    __shared__ float Bg[2][16][64];
    __shared__ float Bu[2][16][64];

    const int tid = threadIdx.x;
    const int tx  = tid & 15;
    const int ty  = tid >> 4;

    // A loader: 128 rows x 16 k; 8 contiguous floats (32B) per thread
    const int arow  = tid & 127;
    const int ahalf = tid >> 7;       // k offset 0 or 8
    int tok = -1;
    if (m0 + arow < cnt) tok = g_pair_token[off + m0 + arow];
    const float* aptr = (tok >= 0) ? (x + (size_t)tok * NH + ahalf * 8) : 0;

    // B loader: 64 rows x 16 k; one float4 per thread, coalesced along k
    const int brow = tid >> 2;        // 0..63
    const int bk   = (tid & 3) * 4;   // 0,4,8,12
    const float* gptr = gW + (size_t)e * NF * NH + (size_t)(f0 + brow) * NH + bk;
    const float* uptr = uW + (size_t)e * NF * NH + (size_t)(f0 + brow) * NH + bk;

    float4 ra0, ra1, rg, ru;
    const float4 z4 = make_float4(0.f, 0.f, 0.f, 0.f);

    // prologue load kt=0
    {
        if (aptr) { ra0 = *(const float4*)(aptr); ra1 = *(const float4*)(aptr + 4); }
        else      { ra0 = z4; ra1 = z4; }
        rg = *(const float4*)(gptr);
        ru = *(const float4*)(uptr);
    }
    {
        const int b = 0;
        As[b][ahalf * 8 + 0][arow] = ra0.x; As[b][ahalf * 8 + 1][arow] = ra0.y;
        As[b][ahalf * 8 + 2][arow] = ra0.z; As[b][ahalf * 8 + 3][arow] = ra0.w;
        As[b][ahalf * 8 + 4][arow] = ra1.x; As[b][ahalf * 8 + 5][arow] = ra1.y;
        As[b][ahalf * 8 + 6][arow] = ra1.z; As[b][ahalf * 8 + 7][arow] = ra1.w;
        Bg[b][bk + 0][brow] = rg.x; Bg[b][bk + 1][brow] = rg.y;
        Bg[b][bk + 2][brow] = rg.z; Bg[b][bk + 3][brow] = rg.w;
        Bu[b][bk + 0][brow] = ru.x; Bu[b][bk + 1][brow] = ru.y;
        Bu[b][bk + 2][brow] = ru.z; Bu[b][bk + 3][brow] = ru.w;
    }
    __syncthreads();

    float cg[8][4], cu[8][4];
#pragma unroll
    for (int i = 0; i < 8; ++i)
#pragma unroll
        for (int j = 0; j < 4; ++j) { cg[i][j] = 0.f; cu[i][j] = 0.f; }

    const int NK = NH / 16;  // 128
    for (int kt = 0; kt < NK; ++kt) {
        const int cur  = kt & 1;
        const bool more = (kt + 1 < NK);
        if (more) {
            const int h0 = (kt + 1) * 16;
            if (aptr) { ra0 = *(const float4*)(aptr + h0); ra1 = *(const float4*)(aptr + h0 + 4); }
            else      { ra0 = z4; ra1 = z4; }
            rg = *(const float4*)(gptr + h0);
            ru = *(const float4*)(uptr + h0);
        }
#pragma unroll
        for (int k = 0; k < 16; ++k) {
            const float4 a0 = *(const float4*)&As[cur][k][ty * 8];
            const float4 a1 = *(const float4*)&As[cur][k][ty * 8 + 4];
            const float4 g4 = *(const float4*)&Bg[cur][k][tx * 4];
            const float4 u4 = *(const float4*)&Bu[cur][k][tx * 4];
            const float av[8] = {a0.x, a0.y, a0.z, a0.w, a1.x, a1.y, a1.z, a1.w};
            const float gv[4] = {g4.x, g4.y, g4.z, g4.w};
            const float uv[4] = {u4.x, u4.y, u4.z, u4.w};
#pragma unroll
            for (int i = 0; i < 8; ++i) {
#pragma unroll
                for (int j = 0; j < 4; ++j) {
                    cg[i][j] = fmaf(av[i], gv[j], cg[i][j]);
                    cu[i][j] = fmaf(av[i], uv[j], cu[i][j]);
                }
            }
        }
        if (more) {
            const int b = (kt + 1) & 1;
            As[b][ahalf * 8 + 0][arow] = ra0.x; As[b][ahalf * 8 + 1][arow] = ra0.y;
            As[b][ahalf * 8 + 2][arow] = ra0.z; As[b][ahalf * 8 + 3][arow] = ra0.w;
            As[b][ahalf * 8 + 4][arow] = ra1.x; As[b][ahalf * 8 + 5][arow] = ra1.y;
            As[b][ahalf * 8 + 6][arow] = ra1.z; As[b][ahalf * 8 + 7][arow] = ra1.w;
            Bg[b][bk + 0][brow] = rg.x; Bg[b][bk + 1][brow] = rg.y;
            Bg[b][bk + 2][brow] = rg.z; Bg[b][bk + 3][brow] = rg.w;
            Bu[b][bk + 0][brow] = ru.x; Bu[b][bk + 1][brow] = ru.y;
            Bu[b][bk + 2][brow] = ru.z; Bu[b][bk + 3][brow] = ru.w;
            __syncthreads();
        }
    }

    // epilogue: silu(g) * u -> g_h1
#pragma unroll
    for (int i = 0; i < 8; ++i) {
        const int m = m0 + ty * 8 + i;
        if (m < cnt) {
            float4 o;
            { const float g = cg[i][0]; o.x = (g / (1.f + __expf(-g))) * cu[i][0]; }
            { const float g = cg[i][1]; o.y = (g / (1.f + __expf(-g))) * cu[i][1]; }
            { const float g = cg[i][2]; o.z = (g / (1.f + __expf(-g))) * cu[i][2]; }
            { const float g = cg[i][3]; o.w = (g / (1.f + __expf(-g))) * cu[i][3]; }
            *(float4*)(g_h1 + (size_t)(off + m) * NF + f0 + tx * 4) = o;
        }
    }
}

// ---------------- GEMM2: ho = h1 dW^T + b -----------------------------------
// tile: 128 pairs x 128 H-cols, BK=16, 256 threads, 8x8 microtile
__global__ void __launch_bounds__(256, 2)
gemm2_k(const float* __restrict__ dW, const float* __restrict__ db) {
    const int e   = blockIdx.z;
    const int cnt = g_counts[e];
    const int m0  = blockIdx.x * 128;
    if (m0 >= cnt) return;
    const int off = g_offsets[e];
    const int n0  = blockIdx.y * 128;

    __shared__ float As[2][16][128];
    __shared__ float Bs[2][16][128];

    const int tid = threadIdx.x;
    const int tx  = tid & 15;
    const int ty  = tid >> 4;

    const int lrow  = tid & 127;
    const int lhalf = tid >> 7;  // k offset 0 or 8
    const bool avalid = (m0 + lrow < cnt);
    const float* aptr = avalid ? (g_h1 + (size_t)(off + m0 + lrow) * NF + lhalf * 8) : 0;
    const float* bptr = dW + (size_t)e * NH * NF + (size_t)(n0 + lrow) * NF + lhalf * 8;

    float4 ra0, ra1, rb0, rb1;
    const float4 z4 = make_float4(0.f, 0.f, 0.f, 0.f);

    {
        if (aptr) { ra0 = *(const float4*)(aptr); ra1 = *(const float4*)(aptr + 4); }
        else      { ra0 = z4; ra1 = z4; }
        rb0 = *(const float4*)(bptr);
        rb1 = *(const float4*)(bptr + 4);
    }
    {
        const int b = 0;
        As[b][lhalf * 8 + 0][lrow] = ra0.x; As[b][lhalf * 8 + 1][lrow] = ra0.y;
        As[b][lhalf * 8 + 2][lrow] = ra0.z; As[b][lhalf * 8 + 3][lrow] = ra0.w;
        As[b][lhalf * 8 + 4][lrow] = ra1.x; As[b][lhalf * 8 + 5][lrow] = ra1.y;
        As[b][lhalf * 8 + 6][lrow] = ra1.z; As[b][lhalf * 8 + 7][lrow] = ra1.w;
        Bs[b][lhalf * 8 + 0][lrow] = rb0.x; Bs[b][lhalf * 8 + 1][lrow] = rb0.y;
        Bs[b][lhalf * 8 + 2][lrow] = rb0.z; Bs[b][lhalf * 8 + 3][lrow] = rb0.w;
        Bs[b][lhalf * 8 + 4][lrow] = rb1.x; Bs[b][lhalf * 8 + 5][lrow] = rb1.y;
        Bs[b][lhalf * 8 + 6][lrow] = rb1.z; Bs[b][lhalf * 8 + 7][lrow] = rb1.w;
    }
    __syncthreads();

    float acc[8][8];
#pragma unroll
    for (int i = 0; i < 8; ++i)
#pragma unroll
        for (int j = 0; j < 8; ++j) acc[i][j] = 0.f;

    const int NK = NF / 16;  // 352
    for (int kt = 0; kt < NK; ++kt) {
        const int cur   = kt & 1;
        const bool more = (kt + 1 < NK);
        if (more) {
            const int k0 = (kt + 1) * 16;
            if (aptr) { ra0 = *(const float4*)(aptr + k0); ra1 = *(const float4*)(aptr + k0 + 4); }
            else      { ra0 = z4; ra1 = z4; }
            rb0 = *(const float4*)(bptr + k0);
            rb1 = *(const float4*)(bptr + k0 + 4);
        }
#pragma unroll
        for (int k = 0; k < 16; ++k) {
            const float4 a0 = *(const float4*)&As[cur][k][ty * 8];
            const float4 a1 = *(const float4*)&As[cur][k][ty * 8 + 4];
            const float4 b0 = *(const float4*)&Bs[cur][k][tx * 8];
            const float4 b1 = *(const float4*)&Bs[cur][k][tx * 8 + 4];
            const float av[8] = {a0.x, a0.y, a0.z, a0.w, a1.x, a1.y, a1.z, a1.w};
            const float bv[8] = {b0.x, b0.y, b0.z, b0.w, b1.x, b1.y, b1.z, b1.w};
#pragma unroll
            for (int i = 0; i < 8; ++i) {
#pragma unroll
                for (int j = 0; j < 8; ++j)
                    acc[i][j] = fmaf(av[i], bv[j], acc[i][j]);
            }
        }
        if (more) {
            const int b = (kt + 1) & 1;
            As[b][lhalf * 8 + 0][lrow] = ra0.x; As[b][lhalf * 8 + 1][lrow] = ra0.y;
            As[b][lhalf * 8 + 2][lrow] = ra0.z; As[b][lhalf * 8 + 3][lrow] = ra0.w;
            As[b][lhalf * 8 + 4][lrow] = ra1.x; As[b][lhalf * 8 + 5][lrow] = ra1.y;
            As[b][lhalf * 8 + 6][lrow] = ra1.z; As[b][lhalf * 8 + 7][lrow] = ra1.w;
            Bs[b][lhalf * 8 + 0][lrow] = rb0.x; Bs[b][lhalf * 8 + 1][lrow] = rb0.y;
            Bs[b][lhalf * 8 + 2][lrow] = rb0.z; Bs[b][lhalf * 8 + 3][lrow] = rb0.w;
            Bs[b][lhalf * 8 + 4][lrow] = rb1.x; Bs[b][lhalf * 8 + 5][lrow] = rb1.y;
            Bs[b][lhalf * 8 + 6][lrow] = rb1.z; Bs[b][lhalf * 8 + 7][lrow] = rb1.w;
            __syncthreads();
        }
    }

#pragma unroll
    for (int i = 0; i < 8; ++i) {
        const int m = m0 + ty * 8 + i;
        if (m < cnt) {
            float* orow = g_ho + (size_t)(off + m) * NH + n0 + tx * 8;
            const float* brow = db + (size_t)e * NH + n0 + tx * 8;
            float4 o0, o1;
            o0.x = acc[i][0] + brow[0]; o0.y = acc[i][1] + brow[1];
            o0.z = acc[i][2] + brow[2]; o0.w = acc[i][3] + brow[3];
            o1.x = acc[i][4] + brow[4]; o1.y = acc[i][5] + brow[5];
            o1.z = acc[i][6] + brow[6]; o1.w = acc[i][7] + brow[7];
            *(float4*)(orow)     = o0;
            *(float4*)(orow + 4) = o1;
        }
    }
}

// ---------------- combine: out = residual + w0*ho0 + w1*ho1 -----------------
__global__ void combine_k(const float* __restrict__ res, float* __restrict__ out) {
    const int idx = blockIdx.x * blockDim.x + threadIdx.x;  // float4 index
    const int NV  = NT * NH / 4;
    if (idx >= NV) return;
    const int t = idx >> 9;        // NH/4 = 512
    const int c = idx & 511;
    const int p0 = g_token_pair[2 * t + 0];
    const int p1 = g_token_pair[2 * t + 1];
    const float w0 = g_top_w[2 * t + 0];
    const float w1 = g_top_w[2 * t + 1];
    const float4 r = ((const float4*)res)[idx];
    const float4 a = *((const float4*)(g_ho + (size_t)p0 * NH) + c);
    const float4 b = *((const float4*)(g_ho + (size_t)p1 * NH) + c);
    float4 o;
    o.x = r.x + w0 * a.x + w1 * b.x;
    o.y = r.y + w0 * a.y + w1 * b.y;
    o.z = r.z + w0 * a.z + w1 * b.z;
    o.w = r.w + w0 * a.w + w1 * b.w;
    ((float4*)out)[idx] = o;
}

// ---------------- launch ----------------------------------------------------
extern "C" void kernel_launch(void* const* d_in, const int* in_sizes, int n_in,
                              void* d_out, int out_size) {
    const float* x    = (const float*)d_in[0];  // hidden_states [B,S,H]
    const float* res  = (const float*)d_in[1];  // residual      [B,S,H]
    const float* rW   = (const float*)d_in[2];  // router_W      [E,H]
    const float* gW   = (const float*)d_in[3];  // gate_W        [E,F,H]
    const float* uW   = (const float*)d_in[4];  // up_W          [E,F,H]
    const float* dW   = (const float*)d_in[5];  // down_W        [E,H,F]
    const float* db   = (const float*)d_in[6];  // down_b        [E,H]
    const int*   elim = (const int*)d_in[7];    // expert_limit

    float* out    = (float*)d_out;
    float* logits = out + (size_t)NT * NH;

    init_k<<<1, 32>>>();
    router_k<<<NT / 8, 256>>>(x, rW, elim, logits);
    scan_k<<<1, 32>>>();
    scatter_k<<<NT / 256, 256>>>();
    gemm1_k<<<dim3(NT / 128, NF / 64, NE), 256>>>(x, gW, uW);
    gemm2_k<<<dim3(NT / 128, NH / 128, NE), 256>>>(dW, db);
    combine_k<<<(NT * NH / 4 + 255) / 256, 256>>>(res, out);
}

// round 3
// speedup vs baseline: 2.4746x; 2.4746x over previous
#include <cuda_runtime.h>
#include <cuda_fp16.h>
#include <math.h>
#include <stdint.h>

#define NB 4
#define NS 2048
#define NH 2048
#define NF 5632
#define NE 8
#define NT (NB * NS)   /* 8192 tokens */
#define NP (NT * 2)    /* 16384 (token, expert) pairs */

// ---------------- scratch (device globals) ----------------------------------
__device__ float g_h1[(size_t)NP * NF];
__device__ float g_ho[(size_t)NP * NH];
__device__ int   g_top_i[NP];
__device__ float g_top_w[NP];
__device__ int   g_pair_token[NP];
__device__ int   g_token_pair[NP];
__device__ int   g_counts[NE];
__device__ int   g_offsets[NE];
__device__ int   g_cursor[NE];

// ---------------- helpers ----------------------------------------------------
__device__ __forceinline__ uint32_t s2u(const void* p) {
    uint32_t a;
    asm("{ .reg .u64 t; cvta.to.shared.u64 t, %1; cvt.u32.u64 %0, t; }" : "=r"(a) : "l"(p));
    return a;
}
__device__ __forceinline__ uint32_t lds32(uint32_t a) {
    uint32_t v;
    asm volatile("ld.shared.b32 %0, [%1];" : "=r"(v) : "r"(a));
    return v;
}
__device__ __forceinline__ void sts128(uint32_t a, uint32_t x, uint32_t y, uint32_t z, uint32_t w) {
    asm volatile("st.shared.v4.b32 [%0], {%1, %2, %3, %4};" :: "r"(a), "r"(x), "r"(y), "r"(z), "r"(w) : "memory");
}
__device__ __forceinline__ void mma16816(float* c, const uint32_t* a, uint32_t b0, uint32_t b1) {
    asm volatile(
        "mma.sync.aligned.m16n8k16.row.col.f32.f16.f16.f32 "
        "{%0,%1,%2,%3}, {%4,%5,%6,%7}, {%8,%9}, {%0,%1,%2,%3};"
        : "+f"(c[0]), "+f"(c[1]), "+f"(c[2]), "+f"(c[3])
        : "r"(a[0]), "r"(a[1]), "r"(a[2]), "r"(a[3]), "r"(b0), "r"(b1));
}
__device__ __forceinline__ uint32_t h2u(__half2 v) { return *reinterpret_cast<uint32_t*>(&v); }

// split 8 fp32 into hi/lo fp16, store 16B each to smem
__device__ __forceinline__ void cvst8(float4 x0, float4 x1, uint32_t hib, uint32_t lob) {
    float f[8] = {x0.x, x0.y, x0.z, x0.w, x1.x, x1.y, x1.z, x1.w};
    uint32_t hr[4], lr[4];
#pragma unroll
    for (int k = 0; k < 4; ++k) {
        __half a = __float2half_rn(f[2 * k]);
        __half b = __float2half_rn(f[2 * k + 1]);
        __half al = __float2half_rn(f[2 * k] - __half2float(a));
        __half bl = __float2half_rn(f[2 * k + 1] - __half2float(b));
        hr[k] = h2u(__halves2half2(a, b));
        lr[k] = h2u(__halves2half2(al, bl));
    }
    sts128(hib, hr[0], hr[1], hr[2], hr[3]);
    sts128(lob, lr[0], lr[1], lr[2], lr[3]);
}

// smem tile geometry: 128 rows x 16 half, padded row stride 48 bytes
#define TROW   48
#define TILE_B (128 * TROW)   /* 6144 */

// ---------------- small kernels ---------------------------------------------
__global__ void init_k() {
    if (threadIdx.x < NE) g_counts[threadIdx.x] = 0;
}

__global__ void router_k(const float* __restrict__ x, const float* __restrict__ rW,
                         const int* __restrict__ elim_p, float* __restrict__ logits_out) {
    const int gwarp = (blockIdx.x * blockDim.x + threadIdx.x) >> 5;
    const int lane  = threadIdx.x & 31;
    if (gwarp >= NT) return;
    const float* xr = x + (size_t)gwarp * NH;
    float acc[NE];
#pragma unroll
    for (int e = 0; e < NE; ++e) acc[e] = 0.f;
    for (int h = lane; h < NH; h += 32) {
        const float xv = xr[h];
#pragma unroll
        for (int e = 0; e < NE; ++e) acc[e] = fmaf(xv, rW[e * NH + h], acc[e]);
    }
#pragma unroll
    for (int e = 0; e < NE; ++e)
#pragma unroll
        for (int o = 16; o > 0; o >>= 1) acc[e] += __shfl_xor_sync(0xffffffffu, acc[e], o);

    if (lane == 0) {
        const int elim = *elim_p;
#pragma unroll
        for (int e = 0; e < NE; ++e) if (e >= elim) acc[e] = -INFINITY;
#pragma unroll
        for (int e = 0; e < NE; ++e) logits_out[gwarp * NE + e] = acc[e];
        int i0 = 0; float v0 = acc[0];
        for (int e = 1; e < NE; ++e) if (acc[e] > v0) { v0 = acc[e]; i0 = e; }
        int i1 = -1; float v1 = -INFINITY;
        for (int e = 0; e < NE; ++e) { if (e == i0) continue; if (acc[e] > v1) { v1 = acc[e]; i1 = e; } }
        float w0, w1;
        if (i1 < 0) { i1 = (i0 + 1) & (NE - 1); w0 = 1.f; w1 = 0.f; }
        else {
            const float ex = expf(v1 - v0);
            w0 = 1.f / (1.f + ex);
            w1 = ex  / (1.f + ex);
        }
        g_top_i[gwarp * 2 + 0] = i0; g_top_i[gwarp * 2 + 1] = i1;
        g_top_w[gwarp * 2 + 0] = w0; g_top_w[gwarp * 2 + 1] = w1;
        atomicAdd(&g_counts[i0], 1);
        atomicAdd(&g_counts[i1], 1);
    }
}

__global__ void scan_k() {
    if (threadIdx.x == 0) {
        int o = 0;
        for (int e = 0; e < NE; ++e) { g_offsets[e] = o; o += g_counts[e]; g_cursor[e] = 0; }
    }
}

__global__ void scatter_k() {
    const int t = blockIdx.x * blockDim.x + threadIdx.x;
    if (t >= NT) return;
#pragma unroll
    for (int k = 0; k < 2; ++k) {
        const int e   = g_top_i[t * 2 + k];
        const int pos = g_offsets[e] + atomicAdd(&g_cursor[e], 1);
        g_pair_token[pos]       = t;
        g_token_pair[t * 2 + k] = pos;
    }
}

// ---------------- GEMM1: mma.sync, gate & up fused --------------------------
// CTA tile 128x128, BK=16 fp32, double-buffered split-fp16 tiles in smem.
// stage layout: Ah Al Gh Gl Uh Ul, each TILE_B
#define G1_STAGE (6 * TILE_B)
#define G1_SMEM  (2 * G1_STAGE)   /* 73728 */

__global__ void __launch_bounds__(256)
gemm1_k(const float* __restrict__ x, const float* __restrict__ gW, const float* __restrict__ uW) {
    const int e   = blockIdx.z;
    const int cnt = g_counts[e];
    const int m0  = blockIdx.x * 128;
    if (m0 >= cnt) return;
    const int off = g_offsets[e];
    const int f0  = blockIdx.y * 128;

    extern __shared__ char smem[];
    const uint32_t sb = s2u(smem);
    const int tid  = threadIdx.x;
    const int wid  = tid >> 5;
    const int lane = tid & 31;
    const int wm = wid & 3, wn = wid >> 2;
    const int g = lane >> 2, t4 = lane & 3;

    // loader: thread -> (row, half): 8 consecutive fp32
    const int row = tid >> 1;
    const int h   = tid & 1;
    int mrow = m0 + row; if (mrow >= cnt) mrow = cnt - 1;
    const int tok = g_pair_token[off + mrow];
    const float* ap = x  + (size_t)tok * NH + h * 8;
    const float* gp = gW + ((size_t)e * NF + (f0 + row)) * NH + h * 8;
    const float* up = uW + ((size_t)e * NF + (f0 + row)) * NH + h * 8;
    const uint32_t soff = row * TROW + h * 16;

    float cg[2][8][4], cu[2][8][4];
#pragma unroll
    for (int i = 0; i < 2; ++i)
#pragma unroll
        for (int j = 0; j < 8; ++j)
#pragma unroll
            for (int q = 0; q < 4; ++q) { cg[i][j][q] = 0.f; cu[i][j][q] = 0.f; }

    // prologue: chunk 0
    {
        float4 r0 = *(const float4*)(ap), r1 = *(const float4*)(ap + 4);
        float4 s0 = *(const float4*)(gp), s1 = *(const float4*)(gp + 4);
        float4 t0 = *(const float4*)(up), t1 = *(const float4*)(up + 4);
        cvst8(r0, r1, sb + 0 * TILE_B + soff, sb + 1 * TILE_B + soff);
        cvst8(s0, s1, sb + 2 * TILE_B + soff, sb + 3 * TILE_B + soff);
        cvst8(t0, t1, sb + 4 * TILE_B + soff, sb + 5 * TILE_B + soff);
    }
    __syncthreads();

    const int NCH = NH / 16;   // 128
    for (int c = 0; c < NCH; ++c) {
        float4 r0, r1, s0, s1, t0, t1;
        const bool more = (c + 1 < NCH);
        if (more) {
            const int k0 = (c + 1) * 16;
            r0 = *(const float4*)(ap + k0); r1 = *(const float4*)(ap + k0 + 4);
            s0 = *(const float4*)(gp + k0); s1 = *(const float4*)(gp + k0 + 4);
            t0 = *(const float4*)(up + k0); t1 = *(const float4*)(up + k0 + 4);
        }

        const uint32_t st = sb + (c & 1) * G1_STAGE;
        // 3 passes: (Ah,Bh) (Ah,Bl) (Al,Bh)
#pragma unroll
        for (int p = 0; p < 3; ++p) {
            const uint32_t ao = (p == 2) ? TILE_B : 0;
            const uint32_t bo = (p == 1) ? TILE_B : 0;
            uint32_t a[2][4];
#pragma unroll
            for (int i = 0; i < 2; ++i) {
                const uint32_t ab = st + ao + (wm * 32 + i * 16 + g) * TROW + t4 * 4;
                a[i][0] = lds32(ab);
                a[i][1] = lds32(ab + 8 * TROW);
                a[i][2] = lds32(ab + 16);
                a[i][3] = lds32(ab + 8 * TROW + 16);
            }
#pragma unroll
            for (int j = 0; j < 8; ++j) {
                const uint32_t nrow = (wn * 64 + j * 8 + g) * TROW + t4 * 4;
                const uint32_t gb = st + 2 * TILE_B + bo + nrow;
                const uint32_t ub = st + 4 * TILE_B + bo + nrow;
                uint32_t b0 = lds32(gb), b1 = lds32(gb + 16);
                mma16816(cg[0][j], a[0], b0, b1);
                mma16816(cg[1][j], a[1], b0, b1);
                uint32_t d0 = lds32(ub), d1 = lds32(ub + 16);
                mma16816(cu[0][j], a[0], d0, d1);
                mma16816(cu[1][j], a[1], d0, d1);
            }
        }

        if (more) {
            __syncthreads();
            const uint32_t st2 = sb + ((c + 1) & 1) * G1_STAGE;
            cvst8(r0, r1, st2 + 0 * TILE_B + soff, st2 + 1 * TILE_B + soff);
            cvst8(s0, s1, st2 + 2 * TILE_B + soff, st2 + 3 * TILE_B + soff);
            cvst8(t0, t1, st2 + 4 * TILE_B + soff, st2 + 5 * TILE_B + soff);
            __syncthreads();
        }
    }

    // epilogue: silu(g)*u -> g_h1
#pragma unroll
    for (int i = 0; i < 2; ++i) {
        const int r0l = wm * 32 + i * 16 + g;       // local row of c0/c1
        const int r1l = r0l + 8;                    // local row of c2/c3
#pragma unroll
        for (int j = 0; j < 8; ++j) {
            const int col = f0 + wn * 64 + j * 8 + t4 * 2;
            if (m0 + r0l < cnt) {
                float gv0 = cg[i][j][0], gv1 = cg[i][j][1];
                float o0 = (gv0 / (1.f + __expf(-gv0))) * cu[i][j][0];
                float o1 = (gv1 / (1.f + __expf(-gv1))) * cu[i][j][1];
                float2 v = make_float2(o0, o1);
                *(float2*)(g_h1 + (size_t)(off + m0 + r0l) * NF + col) = v;
            }
            if (m0 + r1l < cnt) {
                float gv2 = cg[i][j][2], gv3 = cg[i][j][3];
                float o2 = (gv2 / (1.f + __expf(-gv2))) * cu[i][j][2];
                float o3 = (gv3 / (1.f + __expf(-gv3))) * cu[i][j][3];
                float2 v = make_float2(o2, o3);
                *(float2*)(g_h1 + (size_t)(off + m0 + r1l) * NF + col) = v;
            }
        }
    }
}

// ---------------- GEMM2: mma.sync, ho = h1 dW^T + b -------------------------
#define G2_STAGE (4 * TILE_B)
#define G2_SMEM  (2 * G2_STAGE)   /* 49152 */

__global__ void __launch_bounds__(256)
gemm2_k(const float* __restrict__ dW, const float* __restrict__ db) {
    const int e   = blockIdx.z;
    const int cnt = g_counts[e];
    const int m0  = blockIdx.x * 128;
    if (m0 >= cnt) return;
    const int off = g_offsets[e];
    const int n0  = blockIdx.y * 128;

    extern __shared__ char smem[];
    const uint32_t sb = s2u(smem);
    const int tid  = threadIdx.x;
    const int wid  = tid >> 5;
    const int lane = tid & 31;
    const int wm = wid & 3, wn = wid >> 2;
    const int g = lane >> 2, t4 = lane & 3;

    const int row = tid >> 1;
    const int h   = tid & 1;
    int mrow = m0 + row; if (mrow >= cnt) mrow = cnt - 1;
    const float* ap = g_h1 + (size_t)(off + mrow) * NF + h * 8;
    const float* bp = dW + ((size_t)e * NH + (n0 + row)) * NF + h * 8;
    const uint32_t soff = row * TROW + h * 16;

    float acc[2][8][4];
#pragma unroll
    for (int i = 0; i < 2; ++i)
#pragma unroll
        for (int j = 0; j < 8; ++j)
#pragma unroll
            for (int q = 0; q < 4; ++q) acc[i][j][q] = 0.f;

    {
        float4 r0 = *(const float4*)(ap), r1 = *(const float4*)(ap + 4);
        float4 s0 = *(const float4*)(bp), s1 = *(const float4*)(bp + 4);
        cvst8(r0, r1, sb + 0 * TILE_B + soff, sb + 1 * TILE_B + soff);
        cvst8(s0, s1, sb + 2 * TILE_B + soff, sb + 3 * TILE_B + soff);
    }
    __syncthreads();

    const int NCH = NF / 16;   // 352
    for (int c = 0; c < NCH; ++c) {
        float4 r0, r1, s0, s1;
        const bool more = (c + 1 < NCH);
        if (more) {
            const int k0 = (c + 1) * 16;
            r0 = *(const float4*)(ap + k0); r1 = *(const float4*)(ap + k0 + 4);
            s0 = *(const float4*)(bp + k0); s1 = *(const float4*)(bp + k0 + 4);
        }

        const uint32_t st = sb + (c & 1) * G2_STAGE;
#pragma unroll
        for (int p = 0; p < 3; ++p) {
            const uint32_t ao = (p == 2) ? TILE_B : 0;
            const uint32_t bo = (p == 1) ? TILE_B : 0;
            uint32_t a[2][4];
#pragma unroll
            for (int i = 0; i < 2; ++i) {
                const uint32_t ab = st + ao + (wm * 32 + i * 16 + g) * TROW + t4 * 4;
                a[i][0] = lds32(ab);
                a[i][1] = lds32(ab + 8 * TROW);
                a[i][2] = lds32(ab + 16);
                a[i][3] = lds32(ab + 8 * TROW + 16);
            }
#pragma unroll
            for (int j = 0; j < 8; ++j) {
                const uint32_t nb = st + 2 * TILE_B + bo + (wn * 64 + j * 8 + g) * TROW + t4 * 4;
                uint32_t b0 = lds32(nb), b1 = lds32(nb + 16);
                mma16816(acc[0][j], a[0], b0, b1);
                mma16816(acc[1][j], a[1], b0, b1);
            }
        }

        if (more) {
            __syncthreads();
            const uint32_t st2 = sb + ((c + 1) & 1) * G2_STAGE;
            cvst8(r0, r1, st2 + 0 * TILE_B + soff, st2 + 1 * TILE_B + soff);
            cvst8(s0, s1, st2 + 2 * TILE_B + soff, st2 + 3 * TILE_B + soff);
            __syncthreads();
        }
    }

#pragma unroll
    for (int i = 0; i < 2; ++i) {
        const int r0l = wm * 32 + i * 16 + g;
        const int r1l = r0l + 8;
#pragma unroll
        for (int j = 0; j < 8; ++j) {
            const int col = n0 + wn * 64 + j * 8 + t4 * 2;
            const float b0 = db[(size_t)e * NH + col];
            const float b1 = db[(size_t)e * NH + col + 1];
            if (m0 + r0l < cnt) {
                float2 v = make_float2(acc[i][j][0] + b0, acc[i][j][1] + b1);
                *(float2*)(g_ho + (size_t)(off + m0 + r0l) * NH + col) = v;
            }
            if (m0 + r1l < cnt) {
                float2 v = make_float2(acc[i][j][2] + b0, acc[i][j][3] + b1);
                *(float2*)(g_ho + (size_t)(off + m0 + r1l) * NH + col) = v;
            }
        }
    }
}

// ---------------- combine ----------------------------------------------------
__global__ void combine_k(const float* __restrict__ res, float* __restrict__ out) {
    const int idx = blockIdx.x * blockDim.x + threadIdx.x;
    const int NV  = NT * NH / 4;
    if (idx >= NV) return;
    const int t = idx >> 9;
    const int c = idx & 511;
    const int p0 = g_token_pair[2 * t + 0];
    const int p1 = g_token_pair[2 * t + 1];
    const float w0 = g_top_w[2 * t + 0];
    const float w1 = g_top_w[2 * t + 1];
    const float4 r = ((const float4*)res)[idx];
    const float4 a = *((const float4*)(g_ho + (size_t)p0 * NH) + c);
    const float4 b = *((const float4*)(g_ho + (size_t)p1 * NH) + c);
    float4 o;
    o.x = r.x + w0 * a.x + w1 * b.x;
    o.y = r.y + w0 * a.y + w1 * b.y;
    o.z = r.z + w0 * a.z + w1 * b.z;
    o.w = r.w + w0 * a.w + w1 * b.w;
    ((float4*)out)[idx] = o;
}

// ---------------- launch ----------------------------------------------------
extern "C" void kernel_launch(void* const* d_in, const int* in_sizes, int n_in,
                              void* d_out, int out_size) {
    const float* x    = (const float*)d_in[0];
    const float* res  = (const float*)d_in[1];
    const float* rW   = (const float*)d_in[2];
    const float* gW   = (const float*)d_in[3];
    const float* uW   = (const float*)d_in[4];
    const float* dW   = (const float*)d_in[5];
    const float* db   = (const float*)d_in[6];
    const int*   elim = (const int*)d_in[7];

    float* out    = (float*)d_out;
    float* logits = out + (size_t)NT * NH;

    cudaFuncSetAttribute(gemm1_k, cudaFuncAttributeMaxDynamicSharedMemorySize, G1_SMEM);
    cudaFuncSetAttribute(gemm2_k, cudaFuncAttributeMaxDynamicSharedMemorySize, G2_SMEM);

    init_k<<<1, 32>>>();
    router_k<<<NT / 8, 256>>>(x, rW, elim, logits);
    scan_k<<<1, 32>>>();
    scatter_k<<<NT / 256, 256>>>();
    gemm1_k<<<dim3(NT / 128, NF / 128, NE), 256, G1_SMEM>>>(x, gW, uW);
    gemm2_k<<<dim3(NT / 128, NH / 128, NE), 256, G2_SMEM>>>(dW, db);
    combine_k<<<(NT * NH / 4 + 255) / 256, 256>>>(res, out);
}

// round 4
// speedup vs baseline: 2.4826x; 1.0032x over previous
#include <cuda_runtime.h>
#include <cuda_fp16.h>
#include <math.h>
#include <stdint.h>

#define NB 4
#define NS 2048
#define NH 2048
#define NF 5632
#define NE 8
#define NT (NB * NS)   /* 8192 tokens */
#define NP (NT * 2)    /* 16384 (token, expert) pairs */

// ---------------- scratch (device globals) ----------------------------------
__device__ float g_h1[(size_t)NP * NF];
__device__ float g_ho[(size_t)NP * NH];
__device__ int   g_top_i[NP];
__device__ float g_top_w[NP];
__device__ int   g_pair_token[NP];
__device__ int   g_token_pair[NP];
__device__ int   g_counts[NE];
__device__ int   g_offsets[NE];
__device__ int   g_cursor[NE];

// ---------------- helpers ----------------------------------------------------
__device__ __forceinline__ uint32_t s2u(const void* p) {
    uint32_t a;
    asm("{ .reg .u64 t; cvta.to.shared.u64 t, %1; cvt.u32.u64 %0, t; }" : "=r"(a) : "l"(p));
    return a;
}
__device__ __forceinline__ void ldmx4(uint32_t* r, uint32_t a) {
    asm volatile("ldmatrix.sync.aligned.m8n8.x4.shared.b16 {%0,%1,%2,%3}, [%4];"
                 : "=r"(r[0]), "=r"(r[1]), "=r"(r[2]), "=r"(r[3]) : "r"(a));
}
__device__ __forceinline__ void sts128(uint32_t a, uint32_t x, uint32_t y, uint32_t z, uint32_t w) {
    asm volatile("st.shared.v4.b32 [%0], {%1, %2, %3, %4};" :: "r"(a), "r"(x), "r"(y), "r"(z), "r"(w) : "memory");
}
__device__ __forceinline__ void mma16816(float* c, const uint32_t* a, uint32_t b0, uint32_t b1) {
    asm volatile(
        "mma.sync.aligned.m16n8k16.row.col.f32.f16.f16.f32 "
        "{%0,%1,%2,%3}, {%4,%5,%6,%7}, {%8,%9}, {%0,%1,%2,%3};"
        : "+f"(c[0]), "+f"(c[1]), "+f"(c[2]), "+f"(c[3])
        : "r"(a[0]), "r"(a[1]), "r"(a[2]), "r"(a[3]), "r"(b0), "r"(b1));
}
__device__ __forceinline__ uint32_t h2u(__half2 v) { return *reinterpret_cast<uint32_t*>(&v); }

// split 8 fp32 into hi/lo fp16, store 16B each to smem
__device__ __forceinline__ void cvst8(float4 x0, float4 x1, uint32_t hib, uint32_t lob) {
    float f[8] = {x0.x, x0.y, x0.z, x0.w, x1.x, x1.y, x1.z, x1.w};
    uint32_t hr[4], lr[4];
#pragma unroll
    for (int k = 0; k < 4; ++k) {
        __half a = __float2half_rn(f[2 * k]);
        __half b = __float2half_rn(f[2 * k + 1]);
        __half al = __float2half_rn(f[2 * k] - __half2float(a));
        __half bl = __float2half_rn(f[2 * k + 1] - __half2float(b));
        hr[k] = h2u(__halves2half2(a, b));
        lr[k] = h2u(__halves2half2(al, bl));
    }
    sts128(hib, hr[0], hr[1], hr[2], hr[3]);
    sts128(lob, lr[0], lr[1], lr[2], lr[3]);
}

// smem tile geometry: rows x 16 half, padded row stride 48 bytes
#define TROW 48
#define A_TB (128 * TROW)   /* 6144  */
#define B_TB (256 * TROW)   /* 12288 */

// ---------------- small kernels ---------------------------------------------
__global__ void init_k() {
    if (threadIdx.x < NE) g_counts[threadIdx.x] = 0;
}

__global__ void router_k(const float* __restrict__ x, const float* __restrict__ rW,
                         const int* __restrict__ elim_p, float* __restrict__ logits_out) {
    const int gwarp = (blockIdx.x * blockDim.x + threadIdx.x) >> 5;
    const int lane  = threadIdx.x & 31;
    if (gwarp >= NT) return;
    const float* xr = x + (size_t)gwarp * NH;
    float acc[NE];
#pragma unroll
    for (int e = 0; e < NE; ++e) acc[e] = 0.f;
    for (int h = lane; h < NH; h += 32) {
        const float xv = xr[h];
#pragma unroll
        for (int e = 0; e < NE; ++e) acc[e] = fmaf(xv, rW[e * NH + h], acc[e]);
    }
#pragma unroll
    for (int e = 0; e < NE; ++e)
#pragma unroll
        for (int o = 16; o > 0; o >>= 1) acc[e] += __shfl_xor_sync(0xffffffffu, acc[e], o);

    if (lane == 0) {
        const int elim = *elim_p;
#pragma unroll
        for (int e = 0; e < NE; ++e) if (e >= elim) acc[e] = -INFINITY;
#pragma unroll
        for (int e = 0; e < NE; ++e) logits_out[gwarp * NE + e] = acc[e];
        int i0 = 0; float v0 = acc[0];
        for (int e = 1; e < NE; ++e) if (acc[e] > v0) { v0 = acc[e]; i0 = e; }
        int i1 = -1; float v1 = -INFINITY;
        for (int e = 0; e < NE; ++e) { if (e == i0) continue; if (acc[e] > v1) { v1 = acc[e]; i1 = e; } }
        float w0, w1;
        if (i1 < 0) { i1 = (i0 + 1) & (NE - 1); w0 = 1.f; w1 = 0.f; }
        else {
            const float ex = expf(v1 - v0);
            w0 = 1.f / (1.f + ex);
            w1 = ex  / (1.f + ex);
        }
        g_top_i[gwarp * 2 + 0] = i0; g_top_i[gwarp * 2 + 1] = i1;
        g_top_w[gwarp * 2 + 0] = w0; g_top_w[gwarp * 2 + 1] = w1;
        atomicAdd(&g_counts[i0], 1);
        atomicAdd(&g_counts[i1], 1);
    }
}

__global__ void scan_k() {
    if (threadIdx.x == 0) {
        int o = 0;
        for (int e = 0; e < NE; ++e) { g_offsets[e] = o; o += g_counts[e]; g_cursor[e] = 0; }
    }
}

__global__ void scatter_k() {
    const int t = blockIdx.x * blockDim.x + threadIdx.x;
    if (t >= NT) return;
#pragma unroll
    for (int k = 0; k < 2; ++k) {
        const int e   = g_top_i[t * 2 + k];
        const int pos = g_offsets[e] + atomicAdd(&g_cursor[e], 1);
        g_pair_token[pos]       = t;
        g_token_pair[t * 2 + k] = pos;
    }
}

// ---------------- GEMM1: mma.sync + ldmatrix, gate & up fused ----------------
// CTA tile: 128 pairs x 128 F-cols (=256 n-space, gate/up interleaved at 8-col
// granularity). BK=16. 8 warps as 2(m)x4(n), warp tile 64x64.
// B smem row r: block b=r>>3, matrix=b&1 (0 gate,1 up), f_local=(b>>1)*8+(r&7).
// stage layout: Ah | Al | Bh | Bl
#define G1_STAGE (2 * A_TB + 2 * B_TB)   /* 36864 */
#define G1_SMEM  (2 * G1_STAGE)          /* 73728 */
#define OAH 0
#define OAL A_TB
#define OBH (2 * A_TB)
#define OBL (2 * A_TB + B_TB)

__global__ void __launch_bounds__(256)
gemm1_k(const float* __restrict__ x, const float* __restrict__ gW, const float* __restrict__ uW) {
    const int e   = blockIdx.z;
    const int cnt = g_counts[e];
    const int m0  = blockIdx.x * 128;
    if (m0 >= cnt) return;
    const int off = g_offsets[e];
    const int f0  = blockIdx.y * 128;

    extern __shared__ char smem[];
    const uint32_t sb = s2u(smem);
    const int tid  = threadIdx.x;
    const int wid  = tid >> 5;
    const int lane = tid & 31;
    const int wm = wid >> 2, wn = wid & 3;

    // ---- loader mapping (conflict-free STS: quarter-warp = 8 distinct rows) ----
    const int arow  = tid & 127;
    const int ahalf = tid >> 7;
    int mrow = m0 + arow; if (mrow >= cnt) mrow = cnt - 1;
    const int tok = g_pair_token[off + mrow];
    const float* ap = x + (size_t)tok * NH + ahalf * 8;
    const uint32_t a_soff = arow * TROW + ahalf * 16;

    const float* bp[2];
    uint32_t b_soff[2];
#pragma unroll
    for (int it = 0; it < 2; ++it) {
        const int r = arow + 128 * it;
        const int b = r >> 3;
        const int fl = (b >> 1) * 8 + (r & 7);
        const float* w = (b & 1) ? uW : gW;
        bp[it] = w + ((size_t)e * NF + f0 + fl) * NH + ahalf * 8;
        b_soff[it] = r * TROW + ahalf * 16;
    }

    float acc[4][8][4];
#pragma unroll
    for (int i = 0; i < 4; ++i)
#pragma unroll
        for (int j = 0; j < 8; ++j)
#pragma unroll
            for (int q = 0; q < 4; ++q) acc[i][j][q] = 0.f;

    // prologue: chunk 0
    {
        cvst8(*(const float4*)(ap), *(const float4*)(ap + 4),
              sb + OAH + a_soff, sb + OAL + a_soff);
#pragma unroll
        for (int it = 0; it < 2; ++it)
            cvst8(*(const float4*)(bp[it]), *(const float4*)(bp[it] + 4),
                  sb + OBH + b_soff[it], sb + OBL + b_soff[it]);
    }
    __syncthreads();

    // fragment addresses (ldmatrix lane addressing)
    const uint32_t afr = (wm * 64 + (lane & 15)) * TROW + (lane >> 4) * 16;
    const uint32_t bfr = (wn * 64 + ((lane >> 4) << 3) + (lane & 7)) * TROW + ((lane >> 3) & 1) * 16;

    const int NCH = NH / 16;   // 128
    for (int c = 0; c < NCH; ++c) {
        float4 ra0, ra1, rb[2][2];
        const bool more = (c + 1 < NCH);
        if (more) {
            const int k0 = (c + 1) * 16;
            ra0 = *(const float4*)(ap + k0); ra1 = *(const float4*)(ap + k0 + 4);
#pragma unroll
            for (int it = 0; it < 2; ++it) {
                rb[it][0] = *(const float4*)(bp[it] + k0);
                rb[it][1] = *(const float4*)(bp[it] + k0 + 4);
            }
        }

        const uint32_t st = sb + (c & 1) * G1_STAGE;
        uint32_t ah[4][4], al[4][4];
#pragma unroll
        for (int i = 0; i < 4; ++i) {
            ldmx4(ah[i], st + OAH + afr + i * 16 * TROW);
            ldmx4(al[i], st + OAL + afr + i * 16 * TROW);
        }
#pragma unroll
        for (int jp = 0; jp < 4; ++jp) {
            uint32_t bh[4], bl[4];
            ldmx4(bh, st + OBH + bfr + jp * 16 * TROW);
            ldmx4(bl, st + OBL + bfr + jp * 16 * TROW);
#pragma unroll
            for (int i = 0; i < 4; ++i) {
                mma16816(acc[i][2 * jp],     ah[i], bh[0], bh[1]);
                mma16816(acc[i][2 * jp],     ah[i], bl[0], bl[1]);
                mma16816(acc[i][2 * jp],     al[i], bh[0], bh[1]);
                mma16816(acc[i][2 * jp + 1], ah[i], bh[2], bh[3]);
                mma16816(acc[i][2 * jp + 1], ah[i], bl[2], bl[3]);
                mma16816(acc[i][2 * jp + 1], al[i], bh[2], bh[3]);
            }
        }

        if (more) {
            __syncthreads();
            const uint32_t st2 = sb + ((c + 1) & 1) * G1_STAGE;
            cvst8(ra0, ra1, st2 + OAH + a_soff, st2 + OAL + a_soff);
#pragma unroll
            for (int it = 0; it < 2; ++it)
                cvst8(rb[it][0], rb[it][1], st2 + OBH + b_soff[it], st2 + OBL + b_soff[it]);
            __syncthreads();
        }
    }

    // epilogue: gate tile = acc[i][2jp], up tile = acc[i][2jp+1], same F cols
#pragma unroll
    for (int i = 0; i < 4; ++i) {
        const int r0l = wm * 64 + i * 16 + (lane >> 2);
        const int r1l = r0l + 8;
#pragma unroll
        for (int jp = 0; jp < 4; ++jp) {
            const int col = f0 + (wn * 4 + jp) * 8 + (lane & 3) * 2;
            const float* gv = acc[i][2 * jp];
            const float* uv = acc[i][2 * jp + 1];
            if (m0 + r0l < cnt) {
                float o0 = (gv[0] / (1.f + __expf(-gv[0]))) * uv[0];
                float o1 = (gv[1] / (1.f + __expf(-gv[1]))) * uv[1];
                *(float2*)(g_h1 + (size_t)(off + m0 + r0l) * NF + col) = make_float2(o0, o1);
            }
            if (m0 + r1l < cnt) {
                float o2 = (gv[2] / (1.f + __expf(-gv[2]))) * uv[2];
                float o3 = (gv[3] / (1.f + __expf(-gv[3]))) * uv[3];
                *(float2*)(g_h1 + (size_t)(off + m0 + r1l) * NF + col) = make_float2(o2, o3);
            }
        }
    }
}

// ---------------- GEMM2: mma.sync + ldmatrix, ho = h1 dW^T + b ---------------
// CTA tile: 128 pairs x 256 H-cols. 8 warps 2x4, warp tile 64x64.
#define G2_STAGE (2 * A_TB + 2 * B_TB)   /* 36864 */
#define G2_SMEM  (2 * G2_STAGE)

__global__ void __launch_bounds__(256)
gemm2_k(const float* __restrict__ dW, const float* __restrict__ db) {
    const int e   = blockIdx.z;
    const int cnt = g_counts[e];
    const int m0  = blockIdx.x * 128;
    if (m0 >= cnt) return;
    const int off = g_offsets[e];
    const int n0  = blockIdx.y * 256;

    extern __shared__ char smem[];
    const uint32_t sb = s2u(smem);
    const int tid  = threadIdx.x;
    const int wid  = tid >> 5;
    const int lane = tid & 31;
    const int wm = wid >> 2, wn = wid & 3;

    const int arow  = tid & 127;
    const int ahalf = tid >> 7;
    int mrow = m0 + arow; if (mrow >= cnt) mrow = cnt - 1;
    const float* ap = g_h1 + (size_t)(off + mrow) * NF + ahalf * 8;
    const uint32_t a_soff = arow * TROW + ahalf * 16;

    const float* bp[2];
    uint32_t b_soff[2];
#pragma unroll
    for (int it = 0; it < 2; ++it) {
        const int r = arow + 128 * it;
        bp[it] = dW + ((size_t)e * NH + n0 + r) * NF + ahalf * 8;
        b_soff[it] = r * TROW + ahalf * 16;
    }

    float acc[4][8][4];
#pragma unroll
    for (int i = 0; i < 4; ++i)
#pragma unroll
        for (int j = 0; j < 8; ++j)
#pragma unroll
            for (int q = 0; q < 4; ++q) acc[i][j][q] = 0.f;

    {
        cvst8(*(const float4*)(ap), *(const float4*)(ap + 4),
              sb + OAH + a_soff, sb + OAL + a_soff);
#pragma unroll
        for (int it = 0; it < 2; ++it)
            cvst8(*(const float4*)(bp[it]), *(const float4*)(bp[it] + 4),
                  sb + OBH + b_soff[it], sb + OBL + b_soff[it]);
    }
    __syncthreads();

    const uint32_t afr = (wm * 64 + (lane & 15)) * TROW + (lane >> 4) * 16;
    const uint32_t bfr = (wn * 64 + ((lane >> 4) << 3) + (lane & 7)) * TROW + ((lane >> 3) & 1) * 16;

    const int NCH = NF / 16;   // 352
    for (int c = 0; c < NCH; ++c) {
        float4 ra0, ra1, rb[2][2];
        const bool more = (c + 1 < NCH);
        if (more) {
            const int k0 = (c + 1) * 16;
            ra0 = *(const float4*)(ap + k0); ra1 = *(const float4*)(ap + k0 + 4);
#pragma unroll
            for (int it = 0; it < 2; ++it) {
                rb[it][0] = *(const float4*)(bp[it] + k0);
                rb[it][1] = *(const float4*)(bp[it] + k0 + 4);
            }
        }

        const uint32_t st = sb + (c & 1) * G2_STAGE;
        uint32_t ah[4][4], al[4][4];
#pragma unroll
        for (int i = 0; i < 4; ++i) {
            ldmx4(ah[i], st + OAH + afr + i * 16 * TROW);
            ldmx4(al[i], st + OAL + afr + i * 16 * TROW);
        }
#pragma unroll
        for (int jp = 0; jp < 4; ++jp) {
            uint32_t bh[4], bl[4];
            ldmx4(bh, st + OBH + bfr + jp * 16 * TROW);
            ldmx4(bl, st + OBL + bfr + jp * 16 * TROW);
#pragma unroll
            for (int i = 0; i < 4; ++i) {
                mma16816(acc[i][2 * jp],     ah[i], bh[0], bh[1]);
                mma16816(acc[i][2 * jp],     ah[i], bl[0], bl[1]);
                mma16816(acc[i][2 * jp],     al[i], bh[0], bh[1]);
                mma16816(acc[i][2 * jp + 1], ah[i], bh[2], bh[3]);
                mma16816(acc[i][2 * jp + 1], ah[i], bl[2], bl[3]);
                mma16816(acc[i][2 * jp + 1], al[i], bh[2], bh[3]);
            }
        }

        if (more) {
            __syncthreads();
            const uint32_t st2 = sb + ((c + 1) & 1) * G2_STAGE;
            cvst8(ra0, ra1, st2 + OAH + a_soff, st2 + OAL + a_soff);
#pragma unroll
            for (int it = 0; it < 2; ++it)
                cvst8(rb[it][0], rb[it][1], st2 + OBH + b_soff[it], st2 + OBL + b_soff[it]);
            __syncthreads();
        }
    }

#pragma unroll
    for (int i = 0; i < 4; ++i) {
        const int r0l = wm * 64 + i * 16 + (lane >> 2);
        const int r1l = r0l + 8;
#pragma unroll
        for (int j = 0; j < 8; ++j) {
            const int col = n0 + wn * 64 + j * 8 + (lane & 3) * 2;
            const float b0 = db[(size_t)e * NH + col];
            const float b1 = db[(size_t)e * NH + col + 1];
            if (m0 + r0l < cnt)
                *(float2*)(g_ho + (size_t)(off + m0 + r0l) * NH + col) =
                    make_float2(acc[i][j][0] + b0, acc[i][j][1] + b1);
            if (m0 + r1l < cnt)
                *(float2*)(g_ho + (size_t)(off + m0 + r1l) * NH + col) =
                    make_float2(acc[i][j][2] + b0, acc[i][j][3] + b1);
        }
    }
}

// ---------------- combine ----------------------------------------------------
__global__ void combine_k(const float* __restrict__ res, float* __restrict__ out) {
    const int idx = blockIdx.x * blockDim.x + threadIdx.x;
    const int NV  = NT * NH / 4;
    if (idx >= NV) return;
    const int t = idx >> 9;
    const int c = idx & 511;
    const int p0 = g_token_pair[2 * t + 0];
    const int p1 = g_token_pair[2 * t + 1];
    const float w0 = g_top_w[2 * t + 0];
    const float w1 = g_top_w[2 * t + 1];
    const float4 r = ((const float4*)res)[idx];
    const float4 a = *((const float4*)(g_ho + (size_t)p0 * NH) + c);
    const float4 b = *((const float4*)(g_ho + (size_t)p1 * NH) + c);
    float4 o;
    o.x = r.x + w0 * a.x + w1 * b.x;
    o.y = r.y + w0 * a.y + w1 * b.y;
    o.z = r.z + w0 * a.z + w1 * b.z;
    o.w = r.w + w0 * a.w + w1 * b.w;
    ((float4*)out)[idx] = o;
}

// ---------------- launch ----------------------------------------------------
extern "C" void kernel_launch(void* const* d_in, const int* in_sizes, int n_in,
                              void* d_out, int out_size) {
    const float* x    = (const float*)d_in[0];
    const float* res  = (const float*)d_in[1];
    const float* rW   = (const float*)d_in[2];
    const float* gW   = (const float*)d_in[3];
    const float* uW   = (const float*)d_in[4];
    const float* dW   = (const float*)d_in[5];
    const float* db   = (const float*)d_in[6];
    const int*   elim = (const int*)d_in[7];

    float* out    = (float*)d_out;
    float* logits = out + (size_t)NT * NH;

    cudaFuncSetAttribute(gemm1_k, cudaFuncAttributeMaxDynamicSharedMemorySize, G1_SMEM);
    cudaFuncSetAttribute(gemm2_k, cudaFuncAttributeMaxDynamicSharedMemorySize, G2_SMEM);

    init_k<<<1, 32>>>();
    router_k<<<NT / 8, 256>>>(x, rW, elim, logits);
    scan_k<<<1, 32>>>();
    scatter_k<<<NT / 256, 256>>>();
    gemm1_k<<<dim3(NT / 128, NF / 128, NE), 256, G1_SMEM>>>(x, gW, uW);
    gemm2_k<<<dim3(NT / 128, NH / 256, NE), 256, G2_SMEM>>>(dW, db);
    combine_k<<<(NT * NH / 4 + 255) / 256, 256>>>(res, out);
}

// round 5
// speedup vs baseline: 2.7334x; 1.1010x over previous
#include <cuda_runtime.h>
#include <cuda_fp16.h>
#include <math.h>
#include <stdint.h>

#define NB 4
#define NS 2048
#define NH 2048
#define NF 5632
#define NE 8
#define NT (NB * NS)   /* 8192 tokens */
#define NP (NT * 2)    /* 16384 (token, expert) pairs */

// ---------------- scratch (device globals) ----------------------------------
__device__ float g_h1[(size_t)NP * NF];
__device__ float g_ho[(size_t)NP * NH];
__device__ int   g_top_i[NP];
__device__ float g_top_w[NP];
__device__ int   g_pair_token[NP];
__device__ int   g_token_pair[NP];
__device__ int   g_counts[NE];
__device__ int   g_offsets[NE];
__device__ int   g_cursor[NE];

// ---------------- helpers ----------------------------------------------------
__device__ __forceinline__ uint32_t s2u(const void* p) {
    uint32_t a;
    asm("{ .reg .u64 t; cvta.to.shared.u64 t, %1; cvt.u32.u64 %0, t; }" : "=r"(a) : "l"(p));
    return a;
}
__device__ __forceinline__ void ldmx4(uint32_t* r, uint32_t a) {
    asm volatile("ldmatrix.sync.aligned.m8n8.x4.shared.b16 {%0,%1,%2,%3}, [%4];"
                 : "=r"(r[0]), "=r"(r[1]), "=r"(r[2]), "=r"(r[3]) : "r"(a));
}
__device__ __forceinline__ void sts128(uint32_t a, uint32_t x, uint32_t y, uint32_t z, uint32_t w) {
    asm volatile("st.shared.v4.b32 [%0], {%1, %2, %3, %4};" :: "r"(a), "r"(x), "r"(y), "r"(z), "r"(w) : "memory");
}
__device__ __forceinline__ void mma16816(float* c, const uint32_t* a, uint32_t b0, uint32_t b1) {
    asm volatile(
        "mma.sync.aligned.m16n8k16.row.col.f32.f16.f16.f32 "
        "{%0,%1,%2,%3}, {%4,%5,%6,%7}, {%8,%9}, {%0,%1,%2,%3};"
        : "+f"(c[0]), "+f"(c[1]), "+f"(c[2]), "+f"(c[3])
        : "r"(a[0]), "r"(a[1]), "r"(a[2]), "r"(a[3]), "r"(b0), "r"(b1));
}
__device__ __forceinline__ uint32_t h2u(__half2 v) { return *reinterpret_cast<uint32_t*>(&v); }

// split 8 fp32 into hi/lo fp16, store 16B each to smem
__device__ __forceinline__ void cvst8(float4 x0, float4 x1, uint32_t hib, uint32_t lob) {
    float f[8] = {x0.x, x0.y, x0.z, x0.w, x1.x, x1.y, x1.z, x1.w};
    uint32_t hr[4], lr[4];
#pragma unroll
    for (int k = 0; k < 4; ++k) {
        __half a = __float2half_rn(f[2 * k]);
        __half b = __float2half_rn(f[2 * k + 1]);
        __half al = __float2half_rn(f[2 * k] - __half2float(a));
        __half bl = __float2half_rn(f[2 * k + 1] - __half2float(b));
        hr[k] = h2u(__halves2half2(a, b));
        lr[k] = h2u(__halves2half2(al, bl));
    }
    sts128(hib, hr[0], hr[1], hr[2], hr[3]);
    sts128(lob, lr[0], lr[1], lr[2], lr[3]);
}

// convert 8 fp32 to fp16 (hi only), store 16B
__device__ __forceinline__ void cvst8h(float4 x0, float4 x1, uint32_t hib) {
    float f[8] = {x0.x, x0.y, x0.z, x0.w, x1.x, x1.y, x1.z, x1.w};
    uint32_t hr[4];
#pragma unroll
    for (int k = 0; k < 4; ++k) {
        __half a = __float2half_rn(f[2 * k]);
        __half b = __float2half_rn(f[2 * k + 1]);
        hr[k] = h2u(__halves2half2(a, b));
    }
    sts128(hib, hr[0], hr[1], hr[2], hr[3]);
}

// smem tile geometry: rows x 16 half, padded row stride 48 bytes
#define TROW 48
#define A_TB (128 * TROW)   /* 6144  */
#define B_TB (256 * TROW)   /* 12288 */

// ---------------- small kernels ---------------------------------------------
__global__ void init_k() {
    if (threadIdx.x < NE) g_counts[threadIdx.x] = 0;
}

__global__ void router_k(const float* __restrict__ x, const float* __restrict__ rW,
                         const int* __restrict__ elim_p, float* __restrict__ logits_out) {
    const int gwarp = (blockIdx.x * blockDim.x + threadIdx.x) >> 5;
    const int lane  = threadIdx.x & 31;
    if (gwarp >= NT) return;
    const float* xr = x + (size_t)gwarp * NH;
    float acc[NE];
#pragma unroll
    for (int e = 0; e < NE; ++e) acc[e] = 0.f;
    for (int h = lane; h < NH; h += 32) {
        const float xv = xr[h];
#pragma unroll
        for (int e = 0; e < NE; ++e) acc[e] = fmaf(xv, rW[e * NH + h], acc[e]);
    }
#pragma unroll
    for (int e = 0; e < NE; ++e)
#pragma unroll
        for (int o = 16; o > 0; o >>= 1) acc[e] += __shfl_xor_sync(0xffffffffu, acc[e], o);

    if (lane == 0) {
        const int elim = *elim_p;
#pragma unroll
        for (int e = 0; e < NE; ++e) if (e >= elim) acc[e] = -INFINITY;
#pragma unroll
        for (int e = 0; e < NE; ++e) logits_out[gwarp * NE + e] = acc[e];
        int i0 = 0; float v0 = acc[0];
        for (int e = 1; e < NE; ++e) if (acc[e] > v0) { v0 = acc[e]; i0 = e; }
        int i1 = -1; float v1 = -INFINITY;
        for (int e = 0; e < NE; ++e) { if (e == i0) continue; if (acc[e] > v1) { v1 = acc[e]; i1 = e; } }
        float w0, w1;
        if (i1 < 0) { i1 = (i0 + 1) & (NE - 1); w0 = 1.f; w1 = 0.f; }
        else {
            const float ex = expf(v1 - v0);
            w0 = 1.f / (1.f + ex);
            w1 = ex  / (1.f + ex);
        }
        g_top_i[gwarp * 2 + 0] = i0; g_top_i[gwarp * 2 + 1] = i1;
        g_top_w[gwarp * 2 + 0] = w0; g_top_w[gwarp * 2 + 1] = w1;
        atomicAdd(&g_counts[i0], 1);
        atomicAdd(&g_counts[i1], 1);
    }
}

__global__ void scan_k() {
    if (threadIdx.x == 0) {
        int o = 0;
        for (int e = 0; e < NE; ++e) { g_offsets[e] = o; o += g_counts[e]; g_cursor[e] = 0; }
    }
}

__global__ void scatter_k() {
    const int t = blockIdx.x * blockDim.x + threadIdx.x;
    if (t >= NT) return;
#pragma unroll
    for (int k = 0; k < 2; ++k) {
        const int e   = g_top_i[t * 2 + k];
        const int pos = g_offsets[e] + atomicAdd(&g_cursor[e], 1);
        g_pair_token[pos]       = t;
        g_token_pair[t * 2 + k] = pos;
    }
}

// ---------------- GEMM1: 2-pass split-fp16 mma, gate & up fused --------------
// CTA tile: 128 pairs x 128 F-cols (=256 n-space, gate/up interleaved at 8-col
// granularity). BK=16. 8 warps as 2(m)x4(n), warp tile 64x64.
// stage layout: Ah | Al | Bh  (B hi only: 2-pass (Ah+Al)*Bh)
#define STAGE (2 * A_TB + B_TB)   /* 24576 */
#define GSMEM (2 * STAGE)         /* 49152 */
#define OAH 0
#define OAL A_TB
#define OBH (2 * A_TB)

__global__ void __launch_bounds__(256)
gemm1_k(const float* __restrict__ x, const float* __restrict__ gW, const float* __restrict__ uW) {
    const int e   = blockIdx.z;
    const int cnt = g_counts[e];
    const int m0  = blockIdx.x * 128;
    if (m0 >= cnt) return;
    const int off = g_offsets[e];
    const int f0  = blockIdx.y * 128;

    extern __shared__ char smem[];
    const uint32_t sb = s2u(smem);
    const int tid  = threadIdx.x;
    const int wid  = tid >> 5;
    const int lane = tid & 31;
    const int wm = wid >> 2, wn = wid & 3;

    // ---- loader mapping ----
    const int arow  = tid & 127;
    const int ahalf = tid >> 7;
    int mrow = m0 + arow; if (mrow >= cnt) mrow = cnt - 1;
    const int tok = g_pair_token[off + mrow];
    const float* ap = x + (size_t)tok * NH + ahalf * 8;
    const uint32_t a_soff = arow * TROW + ahalf * 16;

    const float* bp[2];
    uint32_t b_soff[2];
#pragma unroll
    for (int it = 0; it < 2; ++it) {
        const int r = arow + 128 * it;
        const int b = r >> 3;
        const int fl = (b >> 1) * 8 + (r & 7);
        const float* w = (b & 1) ? uW : gW;
        bp[it] = w + ((size_t)e * NF + f0 + fl) * NH + ahalf * 8;
        b_soff[it] = r * TROW + ahalf * 16;
    }

    float acc[4][8][4];
#pragma unroll
    for (int i = 0; i < 4; ++i)
#pragma unroll
        for (int j = 0; j < 8; ++j)
#pragma unroll
            for (int q = 0; q < 4; ++q) acc[i][j][q] = 0.f;

    // prologue: chunk 0
    {
        cvst8(*(const float4*)(ap), *(const float4*)(ap + 4),
              sb + OAH + a_soff, sb + OAL + a_soff);
#pragma unroll
        for (int it = 0; it < 2; ++it)
            cvst8h(*(const float4*)(bp[it]), *(const float4*)(bp[it] + 4),
                   sb + OBH + b_soff[it]);
    }
    __syncthreads();

    // fragment addresses (ldmatrix lane addressing)
    const uint32_t afr = (wm * 64 + (lane & 15)) * TROW + (lane >> 4) * 16;
    const uint32_t bfr = (wn * 64 + ((lane >> 4) << 3) + (lane & 7)) * TROW + ((lane >> 3) & 1) * 16;

    const int NCH = NH / 16;   // 128
    for (int c = 0; c < NCH; ++c) {
        float4 ra0, ra1, rb[2][2];
        const bool more = (c + 1 < NCH);
        if (more) {
            const int k0 = (c + 1) * 16;
            ra0 = *(const float4*)(ap + k0); ra1 = *(const float4*)(ap + k0 + 4);
#pragma unroll
            for (int it = 0; it < 2; ++it) {
                rb[it][0] = *(const float4*)(bp[it] + k0);
                rb[it][1] = *(const float4*)(bp[it] + k0 + 4);
            }
        }

        const uint32_t st = sb + (c & 1) * STAGE;
        uint32_t ah[4][4], al[4][4];
#pragma unroll
        for (int i = 0; i < 4; ++i) {
            ldmx4(ah[i], st + OAH + afr + i * 16 * TROW);
            ldmx4(al[i], st + OAL + afr + i * 16 * TROW);
        }
#pragma unroll
        for (int jp = 0; jp < 4; ++jp) {
            uint32_t bh[4];
            ldmx4(bh, st + OBH + bfr + jp * 16 * TROW);
#pragma unroll
            for (int i = 0; i < 4; ++i) {
                mma16816(acc[i][2 * jp],     ah[i], bh[0], bh[1]);
                mma16816(acc[i][2 * jp],     al[i], bh[0], bh[1]);
                mma16816(acc[i][2 * jp + 1], ah[i], bh[2], bh[3]);
                mma16816(acc[i][2 * jp + 1], al[i], bh[2], bh[3]);
            }
        }

        if (more) {
            const uint32_t st2 = sb + ((c + 1) & 1) * STAGE;
            cvst8(ra0, ra1, st2 + OAH + a_soff, st2 + OAL + a_soff);
#pragma unroll
            for (int it = 0; it < 2; ++it)
                cvst8h(rb[it][0], rb[it][1], st2 + OBH + b_soff[it]);
        }
        __syncthreads();
    }

    // epilogue: gate tile = acc[i][2jp], up tile = acc[i][2jp+1], same F cols
#pragma unroll
    for (int i = 0; i < 4; ++i) {
        const int r0l = wm * 64 + i * 16 + (lane >> 2);
        const int r1l = r0l + 8;
#pragma unroll
        for (int jp = 0; jp < 4; ++jp) {
            const int col = f0 + (wn * 4 + jp) * 8 + (lane & 3) * 2;
            const float* gv = acc[i][2 * jp];
            const float* uv = acc[i][2 * jp + 1];
            if (m0 + r0l < cnt) {
                float o0 = (gv[0] / (1.f + __expf(-gv[0]))) * uv[0];
                float o1 = (gv[1] / (1.f + __expf(-gv[1]))) * uv[1];
                *(float2*)(g_h1 + (size_t)(off + m0 + r0l) * NF + col) = make_float2(o0, o1);
            }
            if (m0 + r1l < cnt) {
                float o2 = (gv[2] / (1.f + __expf(-gv[2]))) * uv[2];
                float o3 = (gv[3] / (1.f + __expf(-gv[3]))) * uv[3];
                *(float2*)(g_h1 + (size_t)(off + m0 + r1l) * NF + col) = make_float2(o2, o3);
            }
        }
    }
}

// ---------------- GEMM2: 2-pass split-fp16 mma, ho = h1 dW^T + b -------------
// CTA tile: 128 pairs x 256 H-cols. 8 warps 2x4, warp tile 64x64.
__global__ void __launch_bounds__(256)
gemm2_k(const float* __restrict__ dW, const float* __restrict__ db) {
    const int e   = blockIdx.z;
    const int cnt = g_counts[e];
    const int m0  = blockIdx.x * 128;
    if (m0 >= cnt) return;
    const int off = g_offsets[e];
    const int n0  = blockIdx.y * 256;

    extern __shared__ char smem[];
    const uint32_t sb = s2u(smem);
    const int tid  = threadIdx.x;
    const int wid  = tid >> 5;
    const int lane = tid & 31;
    const int wm = wid >> 2, wn = wid & 3;

    const int arow  = tid & 127;
    const int ahalf = tid >> 7;
    int mrow = m0 + arow; if (mrow >= cnt) mrow = cnt - 1;
    const float* ap = g_h1 + (size_t)(off + mrow) * NF + ahalf * 8;
    const uint32_t a_soff = arow * TROW + ahalf * 16;

    const float* bp[2];
    uint32_t b_soff[2];
#pragma unroll
    for (int it = 0; it < 2; ++it) {
        const int r = arow + 128 * it;
        bp[it] = dW + ((size_t)e * NH + n0 + r) * NF + ahalf * 8;
        b_soff[it] = r * TROW + ahalf * 16;
    }

    float acc[4][8][4];
#pragma unroll
    for (int i = 0; i < 4; ++i)
#pragma unroll
        for (int j = 0; j < 8; ++j)
#pragma unroll
            for (int q = 0; q < 4; ++q) acc[i][j][q] = 0.f;

    {
        cvst8(*(const float4*)(ap), *(const float4*)(ap + 4),
              sb + OAH + a_soff, sb + OAL + a_soff);
#pragma unroll
        for (int it = 0; it < 2; ++it)
            cvst8h(*(const float4*)(bp[it]), *(const float4*)(bp[it] + 4),
                   sb + OBH + b_soff[it]);
    }
    __syncthreads();

    const uint32_t afr = (wm * 64 + (lane & 15)) * TROW + (lane >> 4) * 16;
    const uint32_t bfr = (wn * 64 + ((lane >> 4) << 3) + (lane & 7)) * TROW + ((lane >> 3) & 1) * 16;

    const int NCH = NF / 16;   // 352
    for (int c = 0; c < NCH; ++c) {
        float4 ra0, ra1, rb[2][2];
        const bool more = (c + 1 < NCH);
        if (more) {
            const int k0 = (c + 1) * 16;
            ra0 = *(const float4*)(ap + k0); ra1 = *(const float4*)(ap + k0 + 4);
#pragma unroll
            for (int it = 0; it < 2; ++it) {
                rb[it][0] = *(const float4*)(bp[it] + k0);
                rb[it][1] = *(const float4*)(bp[it] + k0 + 4);
            }
        }

        const uint32_t st = sb + (c & 1) * STAGE;
        uint32_t ah[4][4], al[4][4];
#pragma unroll
        for (int i = 0; i < 4; ++i) {
            ldmx4(ah[i], st + OAH + afr + i * 16 * TROW);
            ldmx4(al[i], st + OAL + afr + i * 16 * TROW);
        }
#pragma unroll
        for (int jp = 0; jp < 4; ++jp) {
            uint32_t bh[4];
            ldmx4(bh, st + OBH + bfr + jp * 16 * TROW);
#pragma unroll
            for (int i = 0; i < 4; ++i) {
                mma16816(acc[i][2 * jp],     ah[i], bh[0], bh[1]);
                mma16816(acc[i][2 * jp],     al[i], bh[0], bh[1]);
                mma16816(acc[i][2 * jp + 1], ah[i], bh[2], bh[3]);
                mma16816(acc[i][2 * jp + 1], al[i], bh[2], bh[3]);
            }
        }

        if (more) {
            const uint32_t st2 = sb + ((c + 1) & 1) * STAGE;
            cvst8(ra0, ra1, st2 + OAH + a_soff, st2 + OAL + a_soff);
#pragma unroll
            for (int it = 0; it < 2; ++it)
                cvst8h(rb[it][0], rb[it][1], st2 + OBH + b_soff[it]);
        }
        __syncthreads();
    }

#pragma unroll
    for (int i = 0; i < 4; ++i) {
        const int r0l = wm * 64 + i * 16 + (lane >> 2);
        const int r1l = r0l + 8;
#pragma unroll
        for (int j = 0; j < 8; ++j) {
            const int col = n0 + wn * 64 + j * 8 + (lane & 3) * 2;
            const float b0 = db[(size_t)e * NH + col];
            const float b1 = db[(size_t)e * NH + col + 1];
            if (m0 + r0l < cnt)
                *(float2*)(g_ho + (size_t)(off + m0 + r0l) * NH + col) =
                    make_float2(acc[i][j][0] + b0, acc[i][j][1] + b1);
            if (m0 + r1l < cnt)
                *(float2*)(g_ho + (size_t)(off + m0 + r1l) * NH + col) =
                    make_float2(acc[i][j][2] + b0, acc[i][j][3] + b1);
        }
    }
}

// ---------------- combine ----------------------------------------------------
__global__ void combine_k(const float* __restrict__ res, float* __restrict__ out) {
    const int idx = blockIdx.x * blockDim.x + threadIdx.x;
    const int NV  = NT * NH / 4;
    if (idx >= NV) return;
    const int t = idx >> 9;
    const int c = idx & 511;
    const int p0 = g_token_pair[2 * t + 0];
    const int p1 = g_token_pair[2 * t + 1];
    const float w0 = g_top_w[2 * t + 0];
    const float w1 = g_top_w[2 * t + 1];
    const float4 r = ((const float4*)res)[idx];
    const float4 a = *((const float4*)(g_ho + (size_t)p0 * NH) + c);
    const float4 b = *((const float4*)(g_ho + (size_t)p1 * NH) + c);
    float4 o;
    o.x = r.x + w0 * a.x + w1 * b.x;
    o.y = r.y + w0 * a.y + w1 * b.y;
    o.z = r.z + w0 * a.z + w1 * b.z;
    o.w = r.w + w0 * a.w + w1 * b.w;
    ((float4*)out)[idx] = o;
}

// ---------------- launch ----------------------------------------------------
extern "C" void kernel_launch(void* const* d_in, const int* in_sizes, int n_in,
                              void* d_out, int out_size) {
    const float* x    = (const float*)d_in[0];
    const float* res  = (const float*)d_in[1];
    const float* rW   = (const float*)d_in[2];
    const float* gW   = (const float*)d_in[3];
    const float* uW   = (const float*)d_in[4];
    const float* dW   = (const float*)d_in[5];
    const float* db   = (const float*)d_in[6];
    const int*   elim = (const int*)d_in[7];

    float* out    = (float*)d_out;
    float* logits = out + (size_t)NT * NH;

    cudaFuncSetAttribute(gemm1_k, cudaFuncAttributeMaxDynamicSharedMemorySize, GSMEM);
    cudaFuncSetAttribute(gemm2_k, cudaFuncAttributeMaxDynamicSharedMemorySize, GSMEM);

    init_k<<<1, 32>>>();
    router_k<<<NT / 8, 256>>>(x, rW, elim, logits);
    scan_k<<<1, 32>>>();
    scatter_k<<<NT / 256, 256>>>();
    gemm1_k<<<dim3(NT / 128, NF / 128, NE), 256, GSMEM>>>(x, gW, uW);
    gemm2_k<<<dim3(NT / 128, NH / 256, NE), 256, GSMEM>>>(dW, db);
    combine_k<<<(NT * NH / 4 + 255) / 256, 256>>>(res, out);
}

// round 6
// speedup vs baseline: 4.3573x; 1.5941x over previous
#include <cuda_runtime.h>
#include <cuda_fp16.h>
#include <math.h>
#include <stdint.h>

#define NB 4
#define NS 2048
#define NH 2048
#define NF 5632
#define NE 8
#define NT (NB * NS)   /* 8192 tokens */
#define NP (NT * 2)    /* 16384 (token, expert) pairs */

// ---------------- scratch (device globals) ----------------------------------
__device__ __half g_h1h[(size_t)NP * NF];
__device__ __half g_h1l[(size_t)NP * NF];
__device__ float  g_ho[(size_t)NP * NH];
__device__ __half g_xh[(size_t)NT * NH];
__device__ __half g_xl[(size_t)NT * NH];
// gemm1 B: per expert, NF/8 blocks x {gate,up} x 8 rows, each row NH halfs
__device__ __half g_w1h[(size_t)NE * NF * 2 * NH];
__device__ __half g_wdh[(size_t)NE * NH * NF];
__device__ int   g_top_i[NP];
__device__ float g_top_w[NP];
__device__ int   g_pair_token[NP];
__device__ int   g_token_pair[NP];
__device__ int   g_counts[NE];
__device__ int   g_offsets[NE];
__device__ int   g_cursor[NE];

// ---------------- helpers ----------------------------------------------------
__device__ __forceinline__ uint32_t s2u(const void* p) {
    uint32_t a;
    asm("{ .reg .u64 t; cvta.to.shared.u64 t, %1; cvt.u32.u64 %0, t; }" : "=r"(a) : "l"(p));
    return a;
}
__device__ __forceinline__ void ldmx4(uint32_t* r, uint32_t a) {
    asm volatile("ldmatrix.sync.aligned.m8n8.x4.shared.b16 {%0,%1,%2,%3}, [%4];"
                 : "=r"(r[0]), "=r"(r[1]), "=r"(r[2]), "=r"(r[3]) : "r"(a));
}
__device__ __forceinline__ void mma16816(float* c, const uint32_t* a, uint32_t b0, uint32_t b1) {
    asm volatile(
        "mma.sync.aligned.m16n8k16.row.col.f32.f16.f16.f32 "
        "{%0,%1,%2,%3}, {%4,%5,%6,%7}, {%8,%9}, {%0,%1,%2,%3};"
        : "+f"(c[0]), "+f"(c[1]), "+f"(c[2]), "+f"(c[3])
        : "r"(a[0]), "r"(a[1]), "r"(a[2]), "r"(a[3]), "r"(b0), "r"(b1));
}
__device__ __forceinline__ uint32_t h2u(__half2 v) { return *reinterpret_cast<uint32_t*>(&v); }

__device__ __forceinline__ void cpa16(uint32_t dst, const void* src) {
    asm volatile("cp.async.cg.shared.global [%0], [%1], 16;" :: "r"(dst), "l"(src));
}
#define CPA_COMMIT() asm volatile("cp.async.commit_group;" ::: "memory")
#define CPA_WAIT2()  asm volatile("cp.async.wait_group 2;" ::: "memory")

// convert 8 fp32 -> 8 fp16 (uint4)
__device__ __forceinline__ uint4 cv8h(float4 a, float4 b) {
    uint4 r;
    r.x = h2u(__floats2half2_rn(a.x, a.y));
    r.y = h2u(__floats2half2_rn(a.z, a.w));
    r.z = h2u(__floats2half2_rn(b.x, b.y));
    r.w = h2u(__floats2half2_rn(b.z, b.w));
    return r;
}

// smem tile geometry: rows x 16 half (32B), padded row stride 48 bytes
#define TROW 48
#define A_TB (128 * TROW)          /* 6144  */
#define B_TB (256 * TROW)          /* 12288 */
#define STAGE (2 * A_TB + B_TB)    /* 24576 */
#define NSTAGE 4
#define GSMEM (NSTAGE * STAGE)     /* 98304 */
#define OAH 0
#define OAL A_TB
#define OBH (2 * A_TB)

// ---------------- small kernels ---------------------------------------------
__global__ void init_k() {
    if (threadIdx.x < NE) g_counts[threadIdx.x] = 0;
}

__global__ void router_k(const float* __restrict__ x, const float* __restrict__ rW,
                         const int* __restrict__ elim_p, float* __restrict__ logits_out) {
    const int gwarp = (blockIdx.x * blockDim.x + threadIdx.x) >> 5;
    const int lane  = threadIdx.x & 31;
    if (gwarp >= NT) return;
    const float* xr = x + (size_t)gwarp * NH;
    float acc[NE];
#pragma unroll
    for (int e = 0; e < NE; ++e) acc[e] = 0.f;
    for (int h = lane; h < NH; h += 32) {
        const float xv = xr[h];
#pragma unroll
        for (int e = 0; e < NE; ++e) acc[e] = fmaf(xv, rW[e * NH + h], acc[e]);
    }
#pragma unroll
    for (int e = 0; e < NE; ++e)
#pragma unroll
        for (int o = 16; o > 0; o >>= 1) acc[e] += __shfl_xor_sync(0xffffffffu, acc[e], o);

    if (lane == 0) {
        const int elim = *elim_p;
#pragma unroll
        for (int e = 0; e < NE; ++e) if (e >= elim) acc[e] = -INFINITY;
#pragma unroll
        for (int e = 0; e < NE; ++e) logits_out[gwarp * NE + e] = acc[e];
        int i0 = 0; float v0 = acc[0];
        for (int e = 1; e < NE; ++e) if (acc[e] > v0) { v0 = acc[e]; i0 = e; }
        int i1 = -1; float v1 = -INFINITY;
        for (int e = 0; e < NE; ++e) { if (e == i0) continue; if (acc[e] > v1) { v1 = acc[e]; i1 = e; } }
        float w0, w1;
        if (i1 < 0) { i1 = (i0 + 1) & (NE - 1); w0 = 1.f; w1 = 0.f; }
        else {
            const float ex = expf(v1 - v0);
            w0 = 1.f / (1.f + ex);
            w1 = ex  / (1.f + ex);
        }
        g_top_i[gwarp * 2 + 0] = i0; g_top_i[gwarp * 2 + 1] = i1;
        g_top_w[gwarp * 2 + 0] = w0; g_top_w[gwarp * 2 + 1] = w1;
        atomicAdd(&g_counts[i0], 1);
        atomicAdd(&g_counts[i1], 1);
    }
}

__global__ void scan_k() {
    if (threadIdx.x == 0) {
        int o = 0;
        for (int e = 0; e < NE; ++e) { g_offsets[e] = o; o += g_counts[e]; g_cursor[e] = 0; }
    }
}

__global__ void scatter_k() {
    const int t = blockIdx.x * blockDim.x + threadIdx.x;
    if (t >= NT) return;
#pragma unroll
    for (int k = 0; k < 2; ++k) {
        const int e   = g_top_i[t * 2 + k];
        const int pos = g_offsets[e] + atomicAdd(&g_cursor[e], 1);
        g_pair_token[pos]       = t;
        g_token_pair[t * 2 + k] = pos;
    }
}

// ---------------- conversion kernels ----------------------------------------
// gate/up -> g_w1h interleaved: row = (e*(NF/8) + f/8)*16 + m*8 + (f&7)
__global__ void cvtw1_k(const float* __restrict__ gW, const float* __restrict__ uW) {
    const size_t idx = (size_t)blockIdx.x * blockDim.x + threadIdx.x;
    if (idx >= (size_t)NE * NF * (NH / 8)) return;
    const int hb  = idx % (NH / 8);
    const int f   = (idx / (NH / 8)) % NF;
    const int e   = idx / ((size_t)NF * (NH / 8));
    const size_t src = ((size_t)e * NF + f) * NH + hb * 8;
    const size_t rowg = ((size_t)e * (NF / 8) + (f >> 3)) * 16 + (f & 7);
    {
        float4 a = *(const float4*)(gW + src), b = *(const float4*)(gW + src + 4);
        *(uint4*)(g_w1h + rowg * NH + hb * 8) = cv8h(a, b);
    }
    {
        float4 a = *(const float4*)(uW + src), b = *(const float4*)(uW + src + 4);
        *(uint4*)(g_w1h + (rowg + 8) * NH + hb * 8) = cv8h(a, b);
    }
}

__global__ void cvtwd_k(const float* __restrict__ dW) {
    const size_t idx = (size_t)blockIdx.x * blockDim.x + threadIdx.x;
    if (idx >= (size_t)NE * NH * (NF / 8)) return;
    const size_t src = idx * 8;
    float4 a = *(const float4*)(dW + src), b = *(const float4*)(dW + src + 4);
    *(uint4*)(g_wdh + src) = cv8h(a, b);
}

__global__ void cvtx_k(const float* __restrict__ x) {
    const size_t idx = (size_t)blockIdx.x * blockDim.x + threadIdx.x;
    if (idx >= (size_t)NT * (NH / 8)) return;
    const size_t src = idx * 8;
    float4 a = *(const float4*)(x + src), b = *(const float4*)(x + src + 4);
    uint4 hi = cv8h(a, b);
    float f[8] = {a.x, a.y, a.z, a.w, b.x, b.y, b.z, b.w};
    uint4 lo;
    {
        const __half2* hp = (const __half2*)&hi;
        uint32_t lr[4];
#pragma unroll
        for (int k = 0; k < 4; ++k)
            lr[k] = h2u(__floats2half2_rn(f[2 * k] - __low2float(hp[k]),
                                          f[2 * k + 1] - __high2float(hp[k])));
        lo = make_uint4(lr[0], lr[1], lr[2], lr[3]);
    }
    *(uint4*)(g_xh + src) = hi;
    *(uint4*)(g_xl + src) = lo;
}

// ---------------- GEMM1: 2-pass split-fp16, cp.async pipeline ----------------
// CTA tile: 128 pairs x 128 F-cols (256 n-space, gate/up interleaved).
__global__ void __launch_bounds__(256)
gemm1_k() {
    const int e   = blockIdx.z;
    const int cnt = g_counts[e];
    const int m0  = blockIdx.x * 128;
    if (m0 >= cnt) return;
    const int off = g_offsets[e];
    const int f0  = blockIdx.y * 128;

    extern __shared__ char smem[];
    const uint32_t sb = s2u(smem);
    const int tid  = threadIdx.x;
    const int wid  = tid >> 5;
    const int lane = tid & 31;
    const int wm = wid >> 2, wn = wid & 3;

    // loader mapping: each thread copies 16B segments (row, half)
    const int lrow = tid >> 1;
    const int half = tid & 1;
    int mrow = m0 + lrow; if (mrow >= cnt) mrow = cnt - 1;
    const int tok = g_pair_token[off + mrow];
    const __half* axh = g_xh + (size_t)tok * NH + half * 8;
    const __half* axl = g_xl + (size_t)tok * NH + half * 8;
    const size_t bbase = ((size_t)e * (NF / 8) + (f0 >> 3)) * 16;
    const __half* bw0 = g_w1h + (bbase + lrow) * NH + half * 8;
    const __half* bw1 = g_w1h + (bbase + 128 + lrow) * NH + half * 8;
    const uint32_t a_soff  = lrow * TROW + half * 16;
    const uint32_t b_soff0 = lrow * TROW + half * 16;
    const uint32_t b_soff1 = (128 + lrow) * TROW + half * 16;

    float acc[4][8][4];
#pragma unroll
    for (int i = 0; i < 4; ++i)
#pragma unroll
        for (int j = 0; j < 8; ++j)
#pragma unroll
            for (int q = 0; q < 4; ++q) acc[i][j][q] = 0.f;

    const int NCH = NH / 16;   // 128
    // prologue: issue stages 0..2
#pragma unroll
    for (int s = 0; s < 3; ++s) {
        const uint32_t st = sb + s * STAGE;
        const int k = s * 16;
        cpa16(st + OAH + a_soff, axh + k);
        cpa16(st + OAL + a_soff, axl + k);
        cpa16(st + OBH + b_soff0, bw0 + k);
        cpa16(st + OBH + b_soff1, bw1 + k);
        CPA_COMMIT();
    }

    const uint32_t afr = (wm * 64 + (lane & 15)) * TROW + (lane >> 4) * 16;
    const uint32_t bfr = (wn * 64 + ((lane >> 4) << 3) + (lane & 7)) * TROW + ((lane >> 3) & 1) * 16;

    for (int c = 0; c < NCH; ++c) {
        CPA_WAIT2();
        __syncthreads();

        // issue chunk c+3 into slot (c+3)%4 (that slot's reads finished at iter c-1)
        if (c + 3 < NCH) {
            const uint32_t st = sb + ((c + 3) & 3) * STAGE;
            const int k = (c + 3) * 16;
            cpa16(st + OAH + a_soff, axh + k);
            cpa16(st + OAL + a_soff, axl + k);
            cpa16(st + OBH + b_soff0, bw0 + k);
            cpa16(st + OBH + b_soff1, bw1 + k);
        }
        CPA_COMMIT();

        const uint32_t st = sb + (c & 3) * STAGE;
        uint32_t ah[4][4], al[4][4];
#pragma unroll
        for (int i = 0; i < 4; ++i) {
            ldmx4(ah[i], st + OAH + afr + i * 16 * TROW);
            ldmx4(al[i], st + OAL + afr + i * 16 * TROW);
        }
#pragma unroll
        for (int jp = 0; jp < 4; ++jp) {
            uint32_t bh[4];
            ldmx4(bh, st + OBH + bfr + jp * 16 * TROW);
#pragma unroll
            for (int i = 0; i < 4; ++i) {
                mma16816(acc[i][2 * jp],     ah[i], bh[0], bh[1]);
                mma16816(acc[i][2 * jp],     al[i], bh[0], bh[1]);
                mma16816(acc[i][2 * jp + 1], ah[i], bh[2], bh[3]);
                mma16816(acc[i][2 * jp + 1], al[i], bh[2], bh[3]);
            }
        }
    }

    // epilogue: silu(gate)*up -> h1 as hi/lo fp16
#pragma unroll
    for (int i = 0; i < 4; ++i) {
        const int r0l = wm * 64 + i * 16 + (lane >> 2);
        const int r1l = r0l + 8;
#pragma unroll
        for (int jp = 0; jp < 4; ++jp) {
            const int col = f0 + (wn * 4 + jp) * 8 + (lane & 3) * 2;
            const float* gv = acc[i][2 * jp];
            const float* uv = acc[i][2 * jp + 1];
            if (m0 + r0l < cnt) {
                float o0 = (gv[0] / (1.f + __expf(-gv[0]))) * uv[0];
                float o1 = (gv[1] / (1.f + __expf(-gv[1]))) * uv[1];
                __half2 h2 = __floats2half2_rn(o0, o1);
                __half2 l2 = __floats2half2_rn(o0 - __low2float(h2), o1 - __high2float(h2));
                const size_t p = (size_t)(off + m0 + r0l) * NF + col;
                *(uint32_t*)(g_h1h + p) = h2u(h2);
                *(uint32_t*)(g_h1l + p) = h2u(l2);
            }
            if (m0 + r1l < cnt) {
                float o2 = (gv[2] / (1.f + __expf(-gv[2]))) * uv[2];
                float o3 = (gv[3] / (1.f + __expf(-gv[3]))) * uv[3];
                __half2 h2 = __floats2half2_rn(o2, o3);
                __half2 l2 = __floats2half2_rn(o2 - __low2float(h2), o3 - __high2float(h2));
                const size_t p = (size_t)(off + m0 + r1l) * NF + col;
                *(uint32_t*)(g_h1h + p) = h2u(h2);
                *(uint32_t*)(g_h1l + p) = h2u(l2);
            }
        }
    }
}

// ---------------- GEMM2: 2-pass split-fp16, cp.async pipeline ----------------
// CTA tile: 128 pairs x 256 H-cols.
__global__ void __launch_bounds__(256)
gemm2_k(const float* __restrict__ db) {
    const int e   = blockIdx.z;
    const int cnt = g_counts[e];
    const int m0  = blockIdx.x * 128;
    if (m0 >= cnt) return;
    const int off = g_offsets[e];
    const int n0  = blockIdx.y * 256;

    extern __shared__ char smem[];
    const uint32_t sb = s2u(smem);
    const int tid  = threadIdx.x;
    const int wid  = tid >> 5;
    const int lane = tid & 31;
    const int wm = wid >> 2, wn = wid & 3;

    const int lrow = tid >> 1;
    const int half = tid & 1;
    int mrow = m0 + lrow; if (mrow >= cnt) mrow = cnt - 1;
    const __half* axh = g_h1h + (size_t)(off + mrow) * NF + half * 8;
    const __half* axl = g_h1l + (size_t)(off + mrow) * NF + half * 8;
    const __half* bw0 = g_wdh + ((size_t)e * NH + n0 + lrow) * NF + half * 8;
    const __half* bw1 = g_wdh + ((size_t)e * NH + n0 + 128 + lrow) * NF + half * 8;
    const uint32_t a_soff  = lrow * TROW + half * 16;
    const uint32_t b_soff0 = lrow * TROW + half * 16;
    const uint32_t b_soff1 = (128 + lrow) * TROW + half * 16;

    float acc[4][8][4];
#pragma unroll
    for (int i = 0; i < 4; ++i)
#pragma unroll
        for (int j = 0; j < 8; ++j)
#pragma unroll
            for (int q = 0; q < 4; ++q) acc[i][j][q] = 0.f;

    const int NCH = NF / 16;   // 352
#pragma unroll
    for (int s = 0; s < 3; ++s) {
        const uint32_t st = sb + s * STAGE;
        const int k = s * 16;
        cpa16(st + OAH + a_soff, axh + k);
        cpa16(st + OAL + a_soff, axl + k);
        cpa16(st + OBH + b_soff0, bw0 + k);
        cpa16(st + OBH + b_soff1, bw1 + k);
        CPA_COMMIT();
    }

    const uint32_t afr = (wm * 64 + (lane & 15)) * TROW + (lane >> 4) * 16;
    const uint32_t bfr = (wn * 64 + ((lane >> 4) << 3) + (lane & 7)) * TROW + ((lane >> 3) & 1) * 16;

    for (int c = 0; c < NCH; ++c) {
        CPA_WAIT2();
        __syncthreads();

        if (c + 3 < NCH) {
            const uint32_t st = sb + ((c + 3) & 3) * STAGE;
            const int k = (c + 3) * 16;
            cpa16(st + OAH + a_soff, axh + k);
            cpa16(st + OAL + a_soff, axl + k);
            cpa16(st + OBH + b_soff0, bw0 + k);
            cpa16(st + OBH + b_soff1, bw1 + k);
        }
        CPA_COMMIT();

        const uint32_t st = sb + (c & 3) * STAGE;
        uint32_t ah[4][4], al[4][4];
#pragma unroll
        for (int i = 0; i < 4; ++i) {
            ldmx4(ah[i], st + OAH + afr + i * 16 * TROW);
            ldmx4(al[i], st + OAL + afr + i * 16 * TROW);
        }
#pragma unroll
        for (int jp = 0; jp < 4; ++jp) {
            uint32_t bh[4];
            ldmx4(bh, st + OBH + bfr + jp * 16 * TROW);
#pragma unroll
            for (int i = 0; i < 4; ++i) {
                mma16816(acc[i][2 * jp],     ah[i], bh[0], bh[1]);
                mma16816(acc[i][2 * jp],     al[i], bh[0], bh[1]);
                mma16816(acc[i][2 * jp + 1], ah[i], bh[2], bh[3]);
                mma16816(acc[i][2 * jp + 1], al[i], bh[2], bh[3]);
            }
        }
    }

#pragma unroll
    for (int i = 0; i < 4; ++i) {
        const int r0l = wm * 64 + i * 16 + (lane >> 2);
        const int r1l = r0l + 8;
#pragma unroll
        for (int j = 0; j < 8; ++j) {
            const int col = n0 + wn * 64 + j * 8 + (lane & 3) * 2;
            const float b0 = db[(size_t)e * NH + col];
            const float b1 = db[(size_t)e * NH + col + 1];
            if (m0 + r0l < cnt)
                *(float2*)(g_ho + (size_t)(off + m0 + r0l) * NH + col) =
                    make_float2(acc[i][j][0] + b0, acc[i][j][1] + b1);
            if (m0 + r1l < cnt)
                *(float2*)(g_ho + (size_t)(off + m0 + r1l) * NH + col) =
                    make_float2(acc[i][j][2] + b0, acc[i][j][3] + b1);
        }
    }
}

// ---------------- combine ----------------------------------------------------
__global__ void combine_k(const float* __restrict__ res, float* __restrict__ out) {
    const int idx = blockIdx.x * blockDim.x + threadIdx.x;
    const int NV  = NT * NH / 4;
    if (idx >= NV) return;
    const int t = idx >> 9;
    const int c = idx & 511;
    const int p0 = g_token_pair[2 * t + 0];
    const int p1 = g_token_pair[2 * t + 1];
    const float w0 = g_top_w[2 * t + 0];
    const float w1 = g_top_w[2 * t + 1];
    const float4 r = ((const float4*)res)[idx];
    const float4 a = *((const float4*)(g_ho + (size_t)p0 * NH) + c);
    const float4 b = *((const float4*)(g_ho + (size_t)p1 * NH) + c);
    float4 o;
    o.x = r.x + w0 * a.x + w1 * b.x;
    o.y = r.y + w0 * a.y + w1 * b.y;
    o.z = r.z + w0 * a.z + w1 * b.z;
    o.w = r.w + w0 * a.w + w1 * b.w;
    ((float4*)out)[idx] = o;
}

// ---------------- launch ----------------------------------------------------
extern "C" void kernel_launch(void* const* d_in, const int* in_sizes, int n_in,
                              void* d_out, int out_size) {
    const float* x    = (const float*)d_in[0];
    const float* res  = (const float*)d_in[1];
    const float* rW   = (const float*)d_in[2];
    const float* gW   = (const float*)d_in[3];
    const float* uW   = (const float*)d_in[4];
    const float* dW   = (const float*)d_in[5];
    const float* db   = (const float*)d_in[6];
    const int*   elim = (const int*)d_in[7];

    float* out    = (float*)d_out;
    float* logits = out + (size_t)NT * NH;

    cudaFuncSetAttribute(gemm1_k, cudaFuncAttributeMaxDynamicSharedMemorySize, GSMEM);
    cudaFuncSetAttribute(gemm2_k, cudaFuncAttributeMaxDynamicSharedMemorySize, GSMEM);

    init_k<<<1, 32>>>();
    router_k<<<NT / 8, 256>>>(x, rW, elim, logits);
    scan_k<<<1, 32>>>();
    scatter_k<<<NT / 256, 256>>>();

    const size_t nw1 = (size_t)NE * NF * (NH / 8);
    cvtw1_k<<<(unsigned)((nw1 + 255) / 256), 256>>>(gW, uW);
    const size_t nwd = (size_t)NE * NH * (NF / 8);
    cvtwd_k<<<(unsigned)((nwd + 255) / 256), 256>>>(dW);
    const size_t nx = (size_t)NT * (NH / 8);
    cvtx_k<<<(unsigned)((nx + 255) / 256), 256>>>(x);

    gemm1_k<<<dim3(NT / 128, NF / 128, NE), 256, GSMEM>>>();
    gemm2_k<<<dim3(NT / 128, NH / 256, NE), 256, GSMEM>>>(db);
    combine_k<<<(NT * NH / 4 + 255) / 256, 256>>>(res, out);
}

// round 8
// speedup vs baseline: 6.4482x; 1.4798x over previous
#include <cuda_runtime.h>
#include <cuda_fp16.h>
#include <math.h>
#include <stdint.h>

#define NB 4
#define NS 2048
#define NH 2048
#define NF 5632
#define NE 8
#define NT (NB * NS)   /* 8192 tokens */
#define NP (NT * 2)    /* 16384 (token, expert) pairs */

// ---------------- scratch (device globals) ----------------------------------
__device__ __half g_h1h[(size_t)NP * NF];
__device__ float  g_ho[(size_t)NP * NH];
__device__ __half g_xh[(size_t)NT * NH];
// gemm1 B: per expert, NF/8 blocks x {gate,up} x 8 rows, each row NH halfs
__device__ __half g_w1h[(size_t)NE * NF * 2 * NH];
__device__ __half g_wdh[(size_t)NE * NH * NF];
__device__ int   g_top_i[NP];
__device__ float g_top_w[NP];
__device__ int   g_pair_token[NP];
__device__ int   g_token_pair[NP];
__device__ int   g_counts[NE];
__device__ int   g_offsets[NE];
__device__ int   g_cursor[NE];

// ---------------- helpers ----------------------------------------------------
__device__ __forceinline__ uint32_t s2u(const void* p) {
    uint32_t a;
    asm("{ .reg .u64 t; cvta.to.shared.u64 t, %1; cvt.u32.u64 %0, t; }" : "=r"(a) : "l"(p));
    return a;
}
__device__ __forceinline__ void ldmx4(uint32_t* r, uint32_t a) {
    asm volatile("ldmatrix.sync.aligned.m8n8.x4.shared.b16 {%0,%1,%2,%3}, [%4];"
                 : "=r"(r[0]), "=r"(r[1]), "=r"(r[2]), "=r"(r[3]) : "r"(a));
}
__device__ __forceinline__ void mma16816(float* c, const uint32_t* a, uint32_t b0, uint32_t b1) {
    asm volatile(
        "mma.sync.aligned.m16n8k16.row.col.f32.f16.f16.f32 "
        "{%0,%1,%2,%3}, {%4,%5,%6,%7}, {%8,%9}, {%0,%1,%2,%3};"
        : "+f"(c[0]), "+f"(c[1]), "+f"(c[2]), "+f"(c[3])
        : "r"(a[0]), "r"(a[1]), "r"(a[2]), "r"(a[3]), "r"(b0), "r"(b1));
}
__device__ __forceinline__ uint32_t h2u(__half2 v) { return *reinterpret_cast<uint32_t*>(&v); }

__device__ __forceinline__ void cpa16(uint32_t dst, const void* src) {
    asm volatile("cp.async.cg.shared.global [%0], [%1], 16;" :: "r"(dst), "l"(src));
}
#define CPA_COMMIT() asm volatile("cp.async.commit_group;" ::: "memory")
#define CPA_WAIT2()  asm volatile("cp.async.wait_group 2;" ::: "memory")

// convert 8 fp32 -> 8 fp16 (uint4)
__device__ __forceinline__ uint4 cv8h(float4 a, float4 b) {
    uint4 r;
    r.x = h2u(__floats2half2_rn(a.x, a.y));
    r.y = h2u(__floats2half2_rn(a.z, a.w));
    r.z = h2u(__floats2half2_rn(b.x, b.y));
    r.w = h2u(__floats2half2_rn(b.z, b.w));
    return r;
}

// smem tile geometry: rows x 16 half (32B), padded row stride 48 bytes
#define TROW 48
#define A_TB (128 * TROW)          /* 6144  */
#define B_TB (256 * TROW)          /* 12288 */
#define STAGE (A_TB + B_TB)        /* 18432 */
#define NSTAGE 4
#define GSMEM (NSTAGE * STAGE)     /* 73728 */
#define OAH 0
#define OBH A_TB

// ---------------- small kernels ---------------------------------------------
__global__ void init_k() {
    if (threadIdx.x < NE) g_counts[threadIdx.x] = 0;
}

__global__ void router_k(const float* __restrict__ x, const float* __restrict__ rW,
                         const int* __restrict__ elim_p, float* __restrict__ logits_out) {
    const int gwarp = (blockIdx.x * blockDim.x + threadIdx.x) >> 5;
    const int lane  = threadIdx.x & 31;
    if (gwarp >= NT) return;
    const float* xr = x + (size_t)gwarp * NH;
    float acc[NE];
#pragma unroll
    for (int e = 0; e < NE; ++e) acc[e] = 0.f;
    for (int h = lane; h < NH; h += 32) {
        const float xv = xr[h];
#pragma unroll
        for (int e = 0; e < NE; ++e) acc[e] = fmaf(xv, rW[e * NH + h], acc[e]);
    }
#pragma unroll
    for (int e = 0; e < NE; ++e)
#pragma unroll
        for (int o = 16; o > 0; o >>= 1) acc[e] += __shfl_xor_sync(0xffffffffu, acc[e], o);

    if (lane == 0) {
        const int elim = *elim_p;
#pragma unroll
        for (int e = 0; e < NE; ++e) if (e >= elim) acc[e] = -INFINITY;
#pragma unroll
        for (int e = 0; e < NE; ++e) logits_out[gwarp * NE + e] = acc[e];
        int i0 = 0; float v0 = acc[0];
        for (int e = 1; e < NE; ++e) if (acc[e] > v0) { v0 = acc[e]; i0 = e; }
        int i1 = -1; float v1 = -INFINITY;
        for (int e = 0; e < NE; ++e) { if (e == i0) continue; if (acc[e] > v1) { v1 = acc[e]; i1 = e; } }
        float w0, w1;
        if (i1 < 0) { i1 = (i0 + 1) & (NE - 1); w0 = 1.f; w1 = 0.f; }
        else {
            const float ex = expf(v1 - v0);
            w0 = 1.f / (1.f + ex);
            w1 = ex  / (1.f + ex);
        }
        g_top_i[gwarp * 2 + 0] = i0; g_top_i[gwarp * 2 + 1] = i1;
        g_top_w[gwarp * 2 + 0] = w0; g_top_w[gwarp * 2 + 1] = w1;
        atomicAdd(&g_counts[i0], 1);
        atomicAdd(&g_counts[i1], 1);
    }
}

__global__ void scan_k() {
    if (threadIdx.x == 0) {
        int o = 0;
        for (int e = 0; e < NE; ++e) { g_offsets[e] = o; o += g_counts[e]; g_cursor[e] = 0; }
    }
}

__global__ void scatter_k() {
    const int t = blockIdx.x * blockDim.x + threadIdx.x;
    if (t >= NT) return;
#pragma unroll
    for (int k = 0; k < 2; ++k) {
        const int e   = g_top_i[t * 2 + k];
        const int pos = g_offsets[e] + atomicAdd(&g_cursor[e], 1);
        g_pair_token[pos]       = t;
        g_token_pair[t * 2 + k] = pos;
    }
}

// ---------------- conversion kernels ----------------------------------------
// gate/up -> g_w1h interleaved: row = (e*(NF/8) + f/8)*16 + m*8 + (f&7)
__global__ void cvtw1_k(const float* __restrict__ gW, const float* __restrict__ uW) {
    const size_t idx = (size_t)blockIdx.x * blockDim.x + threadIdx.x;
    if (idx >= (size_t)NE * NF * (NH / 8)) return;
    const int hb  = idx % (NH / 8);
    const int f   = (idx / (NH / 8)) % NF;
    const int e   = idx / ((size_t)NF * (NH / 8));
    const size_t src = ((size_t)e * NF + f) * NH + hb * 8;
    const size_t rowg = ((size_t)e * (NF / 8) + (f >> 3)) * 16 + (f & 7);
    {
        float4 a = *(const float4*)(gW + src), b = *(const float4*)(gW + src + 4);
        *(uint4*)(g_w1h + rowg * NH + hb * 8) = cv8h(a, b);
    }
    {
        float4 a = *(const float4*)(uW + src), b = *(const float4*)(uW + src + 4);
        *(uint4*)(g_w1h + (rowg + 8) * NH + hb * 8) = cv8h(a, b);
    }
}

__global__ void cvtwd_k(const float* __restrict__ dW) {
    const size_t idx = (size_t)blockIdx.x * blockDim.x + threadIdx.x;
    if (idx >= (size_t)NE * NH * (NF / 8)) return;
    const size_t src = idx * 8;
    float4 a = *(const float4*)(dW + src), b = *(const float4*)(dW + src + 4);
    *(uint4*)(g_wdh + src) = cv8h(a, b);
}

__global__ void cvtx_k(const float* __restrict__ x) {
    const size_t idx = (size_t)blockIdx.x * blockDim.x + threadIdx.x;
    if (idx >= (size_t)NT * (NH / 8)) return;
    const size_t src = idx * 8;
    float4 a = *(const float4*)(x + src), b = *(const float4*)(x + src + 4);
    *(uint4*)(g_xh + src) = cv8h(a, b);
}

// ---------------- GEMM1: fp16 mma, cp.async pipeline -------------------------
// CTA tile: 128 pairs x 128 F-cols (256 n-space, gate/up interleaved).
__global__ void __launch_bounds__(256)
gemm1_k() {
    const int e   = blockIdx.z;
    const int cnt = g_counts[e];
    const int m0  = blockIdx.x * 128;
    if (m0 >= cnt) return;
    const int off = g_offsets[e];
    const int f0  = blockIdx.y * 128;

    extern __shared__ char smem[];
    const uint32_t sb = s2u(smem);
    const int tid  = threadIdx.x;
    const int wid  = tid >> 5;
    const int lane = tid & 31;
    const int wm = wid >> 2, wn = wid & 3;

    // loader mapping: each thread copies 16B segments (row, half)
    const int lrow = tid >> 1;
    const int half = tid & 1;
    int mrow = m0 + lrow; if (mrow >= cnt) mrow = cnt - 1;
    const int tok = g_pair_token[off + mrow];
    const __half* axh = g_xh + (size_t)tok * NH + half * 8;
    const size_t bbase = ((size_t)e * (NF / 8) + (f0 >> 3)) * 16;
    const __half* bw0 = g_w1h + (bbase + lrow) * NH + half * 8;
    const __half* bw1 = g_w1h + (bbase + 128 + lrow) * NH + half * 8;
    const uint32_t a_soff  = lrow * TROW + half * 16;
    const uint32_t b_soff0 = lrow * TROW + half * 16;
    const uint32_t b_soff1 = (128 + lrow) * TROW + half * 16;

    float acc[4][8][4];
#pragma unroll
    for (int i = 0; i < 4; ++i)
#pragma unroll
        for (int j = 0; j < 8; ++j)
#pragma unroll
            for (int q = 0; q < 4; ++q) acc[i][j][q] = 0.f;

    const int NCH = NH / 16;   // 128
    // prologue: issue stages 0..2
#pragma unroll
    for (int s = 0; s < 3; ++s) {
        const uint32_t st = sb + s * STAGE;
        const int k = s * 16;
        cpa16(st + OAH + a_soff, axh + k);
        cpa16(st + OBH + b_soff0, bw0 + k);
        cpa16(st + OBH + b_soff1, bw1 + k);
        CPA_COMMIT();
    }

    const uint32_t afr = (wm * 64 + (lane & 15)) * TROW + (lane >> 4) * 16;
    const uint32_t bfr = (wn * 64 + ((lane >> 4) << 3) + (lane & 7)) * TROW + ((lane >> 3) & 1) * 16;

    for (int c = 0; c < NCH; ++c) {
        CPA_WAIT2();
        __syncthreads();

        // issue chunk c+3 into slot (c+3)%4 (that slot's reads finished at iter c-1)
        if (c + 3 < NCH) {
            const uint32_t st = sb + ((c + 3) & 3) * STAGE;
            const int k = (c + 3) * 16;
            cpa16(st + OAH + a_soff, axh + k);
            cpa16(st + OBH + b_soff0, bw0 + k);
            cpa16(st + OBH + b_soff1, bw1 + k);
        }
        CPA_COMMIT();

        const uint32_t st = sb + (c & 3) * STAGE;
        uint32_t ah[4][4];
#pragma unroll
        for (int i = 0; i < 4; ++i)
            ldmx4(ah[i], st + OAH + afr + i * 16 * TROW);
#pragma unroll
        for (int jp = 0; jp < 4; ++jp) {
            uint32_t bh[4];
            ldmx4(bh, st + OBH + bfr + jp * 16 * TROW);
#pragma unroll
            for (int i = 0; i < 4; ++i) {
                mma16816(acc[i][2 * jp],     ah[i], bh[0], bh[1]);
                mma16816(acc[i][2 * jp + 1], ah[i], bh[2], bh[3]);
            }
        }
    }

    // epilogue: silu(gate)*up -> h1 as fp16
#pragma unroll
    for (int i = 0; i < 4; ++i) {
        const int r0l = wm * 64 + i * 16 + (lane >> 2);
        const int r1l = r0l + 8;
#pragma unroll
        for (int jp = 0; jp < 4; ++jp) {
            const int col = f0 + (wn * 4 + jp) * 8 + (lane & 3) * 2;
            const float* gv = acc[i][2 * jp];
            const float* uv = acc[i][2 * jp + 1];
            if (m0 + r0l < cnt) {
                float o0 = (gv[0] / (1.f + __expf(-gv[0]))) * uv[0];
                float o1 = (gv[1] / (1.f + __expf(-gv[1]))) * uv[1];
                const size_t p = (size_t)(off + m0 + r0l) * NF + col;
                *(uint32_t*)(g_h1h + p) = h2u(__floats2half2_rn(o0, o1));
            }
            if (m0 + r1l < cnt) {
                float o2 = (gv[2] / (1.f + __expf(-gv[2]))) * uv[2];
                float o3 = (gv[3] / (1.f + __expf(-gv[3]))) * uv[3];
                const size_t p = (size_t)(off + m0 + r1l) * NF + col;
                *(uint32_t*)(g_h1h + p) = h2u(__floats2half2_rn(o2, o3));
            }
        }
    }
}

// ---------------- GEMM2: fp16 mma, cp.async pipeline -------------------------
// CTA tile: 128 pairs x 256 H-cols.
__global__ void __launch_bounds__(256)
gemm2_k(const float* __restrict__ db) {
    const int e   = blockIdx.z;
    const int cnt = g_counts[e];
    const int m0  = blockIdx.x * 128;
    if (m0 >= cnt) return;
    const int off = g_offsets[e];
    const int n0  = blockIdx.y * 256;

    extern __shared__ char smem[];
    const uint32_t sb = s2u(smem);
    const int tid  = threadIdx.x;
    const int wid  = tid >> 5;
    const int lane = tid & 31;
    const int wm = wid >> 2, wn = wid & 3;

    const int lrow = tid >> 1;
    const int half = tid & 1;
    int mrow = m0 + lrow; if (mrow >= cnt) mrow = cnt - 1;
    const __half* axh = g_h1h + (size_t)(off + mrow) * NF + half * 8;
    const __half* bw0 = g_wdh + ((size_t)e * NH + n0 + lrow) * NF + half * 8;
    const __half* bw1 = g_wdh + ((size_t)e * NH + n0 + 128 + lrow) * NF + half * 8;
    const uint32_t a_soff  = lrow * TROW + half * 16;
    const uint32_t b_soff0 = lrow * TROW + half * 16;
    const uint32_t b_soff1 = (128 + lrow) * TROW + half * 16;

    float acc[4][8][4];
#pragma unroll
    for (int i = 0; i < 4; ++i)
#pragma unroll
        for (int j = 0; j < 8; ++j)
#pragma unroll
            for (int q = 0; q < 4; ++q) acc[i][j][q] = 0.f;

    const int NCH = NF / 16;   // 352
#pragma unroll
    for (int s = 0; s < 3; ++s) {
        const uint32_t st = sb + s * STAGE;
        const int k = s * 16;
        cpa16(st + OAH + a_soff, axh + k);
        cpa16(st + OBH + b_soff0, bw0 + k);
        cpa16(st + OBH + b_soff1, bw1 + k);
        CPA_COMMIT();
    }

    const uint32_t afr = (wm * 64 + (lane & 15)) * TROW + (lane >> 4) * 16;
    const uint32_t bfr = (wn * 64 + ((lane >> 4) << 3) + (lane & 7)) * TROW + ((lane >> 3) & 1) * 16;

    for (int c = 0; c < NCH; ++c) {
        CPA_WAIT2();
        __syncthreads();

        if (c + 3 < NCH) {
            const uint32_t st = sb + ((c + 3) & 3) * STAGE;
            const int k = (c + 3) * 16;
            cpa16(st + OAH + a_soff, axh + k);
            cpa16(st + OBH + b_soff0, bw0 + k);
            cpa16(st + OBH + b_soff1, bw1 + k);
        }
        CPA_COMMIT();

        const uint32_t st = sb + (c & 3) * STAGE;
        uint32_t ah[4][4];
#pragma unroll
        for (int i = 0; i < 4; ++i)
            ldmx4(ah[i], st + OAH + afr + i * 16 * TROW);
#pragma unroll
        for (int jp = 0; jp < 4; ++jp) {
            uint32_t bh[4];
            ldmx4(bh, st + OBH + bfr + jp * 16 * TROW);
#pragma unroll
            for (int i = 0; i < 4; ++i) {
                mma16816(acc[i][2 * jp],     ah[i], bh[0], bh[1]);
                mma16816(acc[i][2 * jp + 1], ah[i], bh[2], bh[3]);
            }
        }
    }

#pragma unroll
    for (int i = 0; i < 4; ++i) {
        const int r0l = wm * 64 + i * 16 + (lane >> 2);
        const int r1l = r0l + 8;
#pragma unroll
        for (int j = 0; j < 8; ++j) {
            const int col = n0 + wn * 64 + j * 8 + (lane & 3) * 2;
            const float b0 = db[(size_t)e * NH + col];
            const float b1 = db[(size_t)e * NH + col + 1];
            if (m0 + r0l < cnt)
                *(float2*)(g_ho + (size_t)(off + m0 + r0l) * NH + col) =
                    make_float2(acc[i][j][0] + b0, acc[i][j][1] + b1);
            if (m0 + r1l < cnt)
                *(float2*)(g_ho + (size_t)(off + m0 + r1l) * NH + col) =
                    make_float2(acc[i][j][2] + b0, acc[i][j][3] + b1);
        }
    }
}

// ---------------- combine ----------------------------------------------------
__global__ void combine_k(const float* __restrict__ res, float* __restrict__ out) {
    const int idx = blockIdx.x * blockDim.x + threadIdx.x;
    const int NV  = NT * NH / 4;
    if (idx >= NV) return;
    const int t = idx >> 9;
    const int c = idx & 511;
    const int p0 = g_token_pair[2 * t + 0];
    const int p1 = g_token_pair[2 * t + 1];
    const float w0 = g_top_w[2 * t + 0];
    const float w1 = g_top_w[2 * t + 1];
    const float4 r = ((const float4*)res)[idx];
    const float4 a = *((const float4*)(g_ho + (size_t)p0 * NH) + c);
    const float4 b = *((const float4*)(g_ho + (size_t)p1 * NH) + c);
    float4 o;
    o.x = r.x + w0 * a.x + w1 * b.x;
    o.y = r.y + w0 * a.y + w1 * b.y;
    o.z = r.z + w0 * a.z + w1 * b.z;
    o.w = r.w + w0 * a.w + w1 * b.w;
    ((float4*)out)[idx] = o;
}

// ---------------- launch ----------------------------------------------------
extern "C" void kernel_launch(void* const* d_in, const int* in_sizes, int n_in,
                              void* d_out, int out_size) {
    const float* x    = (const float*)d_in[0];
    const float* res  = (const float*)d_in[1];
    const float* rW   = (const float*)d_in[2];
    const float* gW   = (const float*)d_in[3];
    const float* uW   = (const float*)d_in[4];
    const float* dW   = (const float*)d_in[5];
    const float* db   = (const float*)d_in[6];
    const int*   elim = (const int*)d_in[7];

    float* out    = (float*)d_out;
    float* logits = out + (size_t)NT * NH;

    cudaFuncSetAttribute(gemm1_k, cudaFuncAttributeMaxDynamicSharedMemorySize, GSMEM);
    cudaFuncSetAttribute(gemm2_k, cudaFuncAttributeMaxDynamicSharedMemorySize, GSMEM);

    init_k<<<1, 32>>>();
    router_k<<<NT / 8, 256>>>(x, rW, elim, logits);
    scan_k<<<1, 32>>>();
    scatter_k<<<NT / 256, 256>>>();

    const size_t nw1 = (size_t)NE * NF * (NH / 8);
    cvtw1_k<<<(unsigned)((nw1 + 255) / 256), 256>>>(gW, uW);
    const size_t nwd = (size_t)NE * NH * (NF / 8);
    cvtwd_k<<<(unsigned)((nwd + 255) / 256), 256>>>(dW);
    const size_t nx = (size_t)NT * (NH / 8);
    cvtx_k<<<(unsigned)((nx + 255) / 256), 256>>>(x);

    gemm1_k<<<dim3(NT / 128, NF / 128, NE), 256, GSMEM>>>();
    gemm2_k<<<dim3(NT / 128, NH / 256, NE), 256, GSMEM>>>(db);
    combine_k<<<(NT * NH / 4 + 255) / 256, 256>>>(res, out);
}